// round 6
// baseline (speedup 1.0000x reference)
#include <cuda_runtime.h>
#include <cuda_bf16.h>
#include <math.h>
#include <stdint.h>

#define BATCH 4
#define CC 256
#define CI 128
#define NPIX 2304
#define BNEPS 1e-5f
#define NCHUNK 18
#define ETSPLIT 18

// ---------------- scratch ----------------
__device__ float g_PRE[4][BATCH][CI*NPIX];
__device__ float g_ETpart[BATCH][ETSPLIT][CI*CI];
__device__ float g_ET[BATCH][CI*CI];
__device__ float g_A1[BATCH][CI*CI];
__device__ float g_A2[BATCH][CI*CI];
__device__ float g_E[BATCH][NPIX*NPIX];
__device__ float g_Z[2][BATCH][CI*NPIX];
__device__ float g_Y[2][BATCH][CI*NPIX];
__device__ float g_colmax[BATCH][NPIX];
__device__ float g_colrsum[BATCH][NPIX];
__device__ float g_rowmax[BATCH][NPIX];
__device__ float g_rowrsum[BATCH][NPIX];
__device__ float g_pmax[BATCH][NCHUNK][NPIX];
__device__ float g_psum[BATCH][NCHUNK][NPIX];
__device__ float g_WpreH[4][CI*CC];
__device__ float g_WpreL[4][CI*CC];
__device__ float g_bpre[4][CI];
__device__ float g_Wpost[2][CC*CI];
__device__ float g_bpost[2][CC];

// ---------------- fast exp (FMA pipe, no MUFU) ----------------
// valid for x <= 0 (softmax-shifted args); rel err ~3e-7
__device__ __forceinline__ float fexp(float x) {
    float t = fmaxf(x * 1.4426950408889634f, -126.0f);
    float fi = floorf(t);
    float f = t - fi;
    float p =        1.8775767e-3f;
    p = fmaf(p, f,   8.9893397e-3f);
    p = fmaf(p, f,   5.5826318e-2f);
    p = fmaf(p, f,   2.4013971e-1f);
    p = fmaf(p, f,   6.9315169e-1f);
    p = fmaf(p, f,   1.0f);
    return __int_as_float(__float_as_int(p) + ((int)fi << 23));
}

// ---------------- helpers ----------------
__device__ __forceinline__ uint32_t f2t(float x) {
    uint32_t r;
    asm("cvt.rna.tf32.f32 %0, %1;" : "=r"(r) : "f"(x));
    return r;
}
__device__ __forceinline__ void mma8(float c[4], const uint32_t a[4], const uint32_t b[2]) {
    asm volatile(
        "mma.sync.aligned.m16n8k8.row.col.f32.tf32.tf32.f32 "
        "{%0,%1,%2,%3}, {%4,%5,%6,%7}, {%8,%9}, {%0,%1,%2,%3};"
        : "+f"(c[0]), "+f"(c[1]), "+f"(c[2]), "+f"(c[3])
        : "r"(a[0]), "r"(a[1]), "r"(a[2]), "r"(a[3]), "r"(b[0]), "r"(b[1]));
}
__device__ __forceinline__ uint32_t pack_bf(float e, float o) {
    uint32_t r;
    asm("cvt.rn.bf16x2.f32 %0, %1, %2;" : "=r"(r) : "f"(o), "f"(e));
    return r;
}
__device__ __forceinline__ float bf_round(float x) {
    return __bfloat162float(__float2bfloat16(x));
}
__device__ __forceinline__ void mma16bf(float c[4], const uint32_t a[4], const uint32_t b[2]) {
    asm volatile(
        "mma.sync.aligned.m16n8k16.row.col.f32.bf16.bf16.f32 "
        "{%0,%1,%2,%3}, {%4,%5,%6,%7}, {%8,%9}, {%0,%1,%2,%3};"
        : "+f"(c[0]), "+f"(c[1]), "+f"(c[2]), "+f"(c[3])
        : "r"(a[0]), "r"(a[1]), "r"(a[2]), "r"(a[3]), "r"(b[0]), "r"(b[1]));
}
__device__ __forceinline__ void split_pack(float e, float o, uint32_t& hp, uint32_t& lp) {
    float eh = bf_round(e), oh = bf_round(o);
    hp = pack_bf(eh, oh);
    lp = pack_bf(e - eh, o - oh);
}

// ---------------- BN folding ----------------
__global__ void k_fold(const float* __restrict__ bn_pre, const float* __restrict__ w_pre,
                       const float* __restrict__ b_pre, const float* __restrict__ w_post,
                       const float* __restrict__ b_post, const float* __restrict__ bn_post)
{
    int tid = threadIdx.x;
    if (blockIdx.x == 0) {
        int i = tid >> 7, o = tid & 127;
        const float* bp = bn_pre + i * 4 * CC;
        const float* w  = w_pre + (i * CI + o) * CC;
        float acc = b_pre[i * CI + o];
        for (int c = 0; c < CC; c++) {
            float s = bp[c] * rsqrtf(bp[3 * CC + c] + BNEPS);
            float t = bp[CC + c] - bp[2 * CC + c] * s;
            float wv = w[c] * s;
            float h = bf_round(wv);
            g_WpreH[i][o * CC + c] = h;
            g_WpreL[i][o * CC + c] = wv - h;
            acc += w[c] * t;
        }
        g_bpre[i][o] = acc;
    } else {
        int i = tid >> 8, o = tid & 255;
        const float* bp = bn_post + i * 4 * CC;
        float s = bp[o] * rsqrtf(bp[3 * CC + o] + BNEPS);
        const float* w = w_post + (i * CC + o) * CI;
        for (int c = 0; c < CI; c++)
            g_Wpost[i][o * CI + c] = w[c] * s;
        g_bpost[i][o] = b_post[i * CC + o] * s + bp[CC + o] - bp[2 * CC + o] * s;
    }
}

// ======================================================================
// k_pre_bf16 (unchanged from R5)
// ======================================================================
__global__ void __launch_bounds__(256) k_pre_bf16(const float* __restrict__ x1,
                                                  const float* __restrict__ x2)
{
    int i = blockIdx.z >> 2, b = blockIdx.z & 3;
    int n0 = blockIdx.x * 64;
    const float* __restrict__ AHf = g_WpreH[i];
    const float* __restrict__ ALf = g_WpreL[i];
    const float* __restrict__ Bsrc = ((i & 1) ? x2 : x1) + b * CC * NPIX;

    __shared__ uint32_t Ah[128][20], Al[128][20], Bh[16][72], Bl[16][72];

    int tid = threadIdx.x;
    int wid = tid >> 5, lane = tid & 31;
    int g = lane >> 2, tig = lane & 3;
    int wm = (wid & 3) * 32, wn = (wid >> 2) * 32;

    int am = tid >> 2, akq = (tid & 3) * 8;
    int bk2 = tid >> 4, bn4 = (tid & 15) * 4;

    float4 sh0[2], sh1[2], sl0[2], sl1[2], sbe, sbo;
    float c[2][4][4] = {};

    auto loadT = [&](int k0) {
#pragma unroll
        for (int it = 0; it < 2; it++) {
            int m = am + it * 64;
            sh0[it] = *(const float4*)&AHf[m * CC + k0 + akq];
            sh1[it] = *(const float4*)&AHf[m * CC + k0 + akq + 4];
            sl0[it] = *(const float4*)&ALf[m * CC + k0 + akq];
            sl1[it] = *(const float4*)&ALf[m * CC + k0 + akq + 4];
        }
        const float* be = &Bsrc[(k0 + 2 * bk2) * NPIX + n0 + bn4];
        sbe = *(const float4*)be;
        sbo = *(const float4*)(be + NPIX);
    };
    auto storeT = [&]() {
#pragma unroll
        for (int it = 0; it < 2; it++) {
            int m = am + it * 64, kq2 = akq >> 1;
            *(uint4*)&Ah[m][kq2] = make_uint4(
                pack_bf(sh0[it].x, sh0[it].y), pack_bf(sh0[it].z, sh0[it].w),
                pack_bf(sh1[it].x, sh1[it].y), pack_bf(sh1[it].z, sh1[it].w));
            *(uint4*)&Al[m][kq2] = make_uint4(
                pack_bf(sl0[it].x, sl0[it].y), pack_bf(sl0[it].z, sl0[it].w),
                pack_bf(sl1[it].x, sl1[it].y), pack_bf(sl1[it].z, sl1[it].w));
        }
        uint32_t h0,l0,h1,l1,h2,l2,h3,l3;
        split_pack(sbe.x, sbo.x, h0, l0); split_pack(sbe.y, sbo.y, h1, l1);
        split_pack(sbe.z, sbo.z, h2, l2); split_pack(sbe.w, sbo.w, h3, l3);
        *(uint4*)&Bh[bk2][bn4] = make_uint4(h0, h1, h2, h3);
        *(uint4*)&Bl[bk2][bn4] = make_uint4(l0, l1, l2, l3);
    };

    loadT(0); storeT(); __syncthreads();
    for (int t = 0; t < 8; t++) {
        if (t < 7) loadT((t + 1) * 32);
#pragma unroll
        for (int kk2 = 0; kk2 < 16; kk2 += 8) {
            uint32_t ah[2][4], al[2][4];
#pragma unroll
            for (int mi = 0; mi < 2; mi++) {
                int mr = wm + mi * 16;
                ah[mi][0]=Ah[mr+g  ][kk2+tig  ]; ah[mi][1]=Ah[mr+g+8][kk2+tig  ];
                ah[mi][2]=Ah[mr+g  ][kk2+tig+4]; ah[mi][3]=Ah[mr+g+8][kk2+tig+4];
                al[mi][0]=Al[mr+g  ][kk2+tig  ]; al[mi][1]=Al[mr+g+8][kk2+tig  ];
                al[mi][2]=Al[mr+g  ][kk2+tig+4]; al[mi][3]=Al[mr+g+8][kk2+tig+4];
            }
#pragma unroll
            for (int ni = 0; ni < 4; ni++) {
                uint32_t bh[2], bl[2];
                bh[0]=Bh[kk2+tig  ][wn+ni*8+g]; bh[1]=Bh[kk2+tig+4][wn+ni*8+g];
                bl[0]=Bl[kk2+tig  ][wn+ni*8+g]; bl[1]=Bl[kk2+tig+4][wn+ni*8+g];
#pragma unroll
                for (int mi = 0; mi < 2; mi++) {
                    mma16bf(c[mi][ni], ah[mi], bh);
                    mma16bf(c[mi][ni], ah[mi], bl);
                    mma16bf(c[mi][ni], al[mi], bh);
                }
            }
        }
        __syncthreads();
        if (t < 7) storeT();
        __syncthreads();
    }

    float* Cout = g_PRE[i][b];
#pragma unroll
    for (int mi = 0; mi < 2; mi++) {
#pragma unroll
        for (int ni = 0; ni < 4; ni++) {
            int row = wm + mi * 16 + g;
            int col = n0 + wn + ni * 8 + tig * 2;
            float b0 = g_bpre[i][row], b1 = g_bpre[i][row + 8];
            *(float2*)&Cout[row * NPIX + col] =
                make_float2(c[mi][ni][0] + b0, c[mi][ni][1] + b0);
            *(float2*)&Cout[(row + 8) * NPIX + col] =
                make_float2(c[mi][ni][2] + b1, c[mi][ni][3] + b1);
        }
    }
}

// ======================================================================
// k_etime_bf16 (unchanged from R5)
// ======================================================================
__global__ void __launch_bounds__(256) k_etime_bf16()
{
    int b = blockIdx.z, ks = blockIdx.y;
    int n0 = blockIdx.x * 64;
    int kbeg = ks * (NPIX / ETSPLIT);
    const float* __restrict__ Tm = g_PRE[2][b];
    const float* __restrict__ Pm = g_PRE[3][b];

    __shared__ uint32_t Ah[128][20], Al[128][20], Bh[64][20], Bl[64][20];

    int tid = threadIdx.x;
    int wid = tid >> 5, lane = tid & 31;
    int g = lane >> 2, tig = lane & 3;
    int wm = (wid & 3) * 32, wn = (wid >> 2) * 32;

    int am = tid >> 1, ak = (tid & 1) * 16;
    int bn = tid >> 2, bk = (tid & 3) * 8;

    float4 sA[4], sB[2];
    float c[2][4][4] = {};

    auto loadT = [&](int k0) {
#pragma unroll
        for (int q = 0; q < 4; q++) sA[q] = *(const float4*)&Tm[am * NPIX + k0 + ak + q * 4];
#pragma unroll
        for (int q = 0; q < 2; q++) sB[q] = *(const float4*)&Pm[(n0 + bn) * NPIX + k0 + bk + q * 4];
    };
    auto storeT = [&]() {
#pragma unroll
        for (int q = 0; q < 4; q++) {
            uint32_t h0,l0,h1,l1;
            split_pack(sA[q].x, sA[q].y, h0, l0);
            split_pack(sA[q].z, sA[q].w, h1, l1);
            int k2 = (ak >> 1) + q * 2;
            Ah[am][k2] = h0; Ah[am][k2+1] = h1;
            Al[am][k2] = l0; Al[am][k2+1] = l1;
        }
#pragma unroll
        for (int q = 0; q < 2; q++) {
            uint32_t h0,l0,h1,l1;
            split_pack(sB[q].x, sB[q].y, h0, l0);
            split_pack(sB[q].z, sB[q].w, h1, l1);
            int k2 = (bk >> 1) + q * 2;
            Bh[bn][k2] = h0; Bh[bn][k2+1] = h1;
            Bl[bn][k2] = l0; Bl[bn][k2+1] = l1;
        }
    };

    loadT(kbeg); storeT(); __syncthreads();
    for (int t = 0; t < 4; t++) {
        if (t < 3) loadT(kbeg + (t + 1) * 32);
#pragma unroll
        for (int kk2 = 0; kk2 < 16; kk2 += 8) {
            uint32_t ah[2][4], al[2][4];
#pragma unroll
            for (int mi = 0; mi < 2; mi++) {
                int mr = wm + mi * 16;
                ah[mi][0]=Ah[mr+g  ][kk2+tig  ]; ah[mi][1]=Ah[mr+g+8][kk2+tig  ];
                ah[mi][2]=Ah[mr+g  ][kk2+tig+4]; ah[mi][3]=Ah[mr+g+8][kk2+tig+4];
                al[mi][0]=Al[mr+g  ][kk2+tig  ]; al[mi][1]=Al[mr+g+8][kk2+tig  ];
                al[mi][2]=Al[mr+g  ][kk2+tig+4]; al[mi][3]=Al[mr+g+8][kk2+tig+4];
            }
#pragma unroll
            for (int ni = 0; ni < 4; ni++) {
                int nr = wn + ni * 8 + g;
                uint32_t bh[2], bl[2];
                bh[0]=Bh[nr][kk2+tig]; bh[1]=Bh[nr][kk2+tig+4];
                bl[0]=Bl[nr][kk2+tig]; bl[1]=Bl[nr][kk2+tig+4];
#pragma unroll
                for (int mi = 0; mi < 2; mi++) {
                    mma16bf(c[mi][ni], ah[mi], bh);
                    mma16bf(c[mi][ni], ah[mi], bl);
                    mma16bf(c[mi][ni], al[mi], bh);
                }
            }
        }
        __syncthreads();
        if (t < 3) storeT();
        __syncthreads();
    }

    float* outp = g_ETpart[b][ks];
#pragma unroll
    for (int mi = 0; mi < 2; mi++) {
#pragma unroll
        for (int ni = 0; ni < 4; ni++) {
            int row = wm + mi * 16 + g;
            int col = n0 + wn + ni * 8 + tig * 2;
            *(float2*)&outp[row * CI + col]       = make_float2(c[mi][ni][0], c[mi][ni][1]);
            *(float2*)&outp[(row + 8) * CI + col] = make_float2(c[mi][ni][2], c[mi][ni][3]);
        }
    }
}

__global__ void k_etreduce()
{
    int b = blockIdx.y, idx = blockIdx.x * 256 + threadIdx.x;
    float s = 0.f;
#pragma unroll
    for (int p = 0; p < ETSPLIT; p++) s += g_ETpart[b][p][idx];
    g_ET[b][idx] = s;
}

__global__ void k_softmax_time()
{
    int b = blockIdx.x, t = threadIdx.x;
    const float* ET = g_ET[b];
    float mx = -3.0e38f;
    for (int d = 0; d < CI; d++) mx = fmaxf(mx, ET[t * CI + d]);
    float s = 0.f;
    for (int d = 0; d < CI; d++) s += fexp(ET[t * CI + d] - mx);
    float rs = 1.f / s;
    for (int d = 0; d < CI; d++) g_A2[b][t * CI + d] = fexp(ET[t * CI + d] - mx) * rs;
    mx = -3.0e38f;
    for (int d = 0; d < CI; d++) mx = fmaxf(mx, ET[d * CI + t]);
    s = 0.f;
    for (int d = 0; d < CI; d++) s += fexp(ET[d * CI + t] - mx);
    rs = 1.f / s;
    for (int d = 0; d < CI; d++) g_A1[b][t * CI + d] = fexp(ET[d * CI + t] - mx) * rs;
}

// ======================================================================
// k_espace_bf16 (unchanged from R5)
// ======================================================================
__global__ void __launch_bounds__(256) k_espace_bf16()
{
    int b = blockIdx.z;
    int row0 = blockIdx.y * 128, col0 = blockIdx.x * 64;
    const float* __restrict__ T = g_PRE[2][b];
    const float* __restrict__ P = g_PRE[3][b];

    __shared__ uint32_t Ah[16][136], Al[16][136];
    __shared__ uint32_t Bh[16][72],  Bl[16][72];

    int tid = threadIdx.x;
    int wid = tid >> 5, lane = tid & 31;
    int g = lane >> 2, tig = lane & 3;
    int wm = (wid & 3) * 32, wn = (wid >> 2) * 32;

    int ak2 = tid >> 5, an4 = (tid & 31) * 4;
    int bk2 = tid >> 4, bm4 = (tid & 15) * 4;

    float4 sAe[2], sAo[2], sBe, sBo;
    float c[2][4][4] = {};

    auto loadT = [&](int k0) {
#pragma unroll
        for (int it = 0; it < 2; it++) {
            const float* te = &T[(k0 + 2 * (ak2 + it * 8)) * NPIX + row0 + an4];
            sAe[it] = *(const float4*)te;
            sAo[it] = *(const float4*)(te + NPIX);
        }
        const float* pe = &P[(k0 + 2 * bk2) * NPIX + col0 + bm4];
        sBe = *(const float4*)pe;
        sBo = *(const float4*)(pe + NPIX);
    };
    auto storeT = [&]() {
#pragma unroll
        for (int it = 0; it < 2; it++) {
            uint32_t h0,l0,h1,l1,h2,l2,h3,l3;
            split_pack(sAe[it].x, sAo[it].x, h0, l0); split_pack(sAe[it].y, sAo[it].y, h1, l1);
            split_pack(sAe[it].z, sAo[it].z, h2, l2); split_pack(sAe[it].w, sAo[it].w, h3, l3);
            int r = ak2 + it * 8;
            *(uint4*)&Ah[r][an4] = make_uint4(h0, h1, h2, h3);
            *(uint4*)&Al[r][an4] = make_uint4(l0, l1, l2, l3);
        }
        uint32_t h0,l0,h1,l1,h2,l2,h3,l3;
        split_pack(sBe.x, sBo.x, h0, l0); split_pack(sBe.y, sBo.y, h1, l1);
        split_pack(sBe.z, sBo.z, h2, l2); split_pack(sBe.w, sBo.w, h3, l3);
        *(uint4*)&Bh[bk2][bm4] = make_uint4(h0, h1, h2, h3);
        *(uint4*)&Bl[bk2][bm4] = make_uint4(l0, l1, l2, l3);
    };

    loadT(0); storeT(); __syncthreads();
    for (int t = 0; t < 4; t++) {
        if (t < 3) loadT((t + 1) * 32);
#pragma unroll
        for (int kk2 = 0; kk2 < 16; kk2 += 8) {
            uint32_t ah[2][4], al[2][4];
#pragma unroll
            for (int mi = 0; mi < 2; mi++) {
                int mr = wm + mi * 16;
                ah[mi][0] = Ah[kk2+tig  ][mr + g    ];
                ah[mi][1] = Ah[kk2+tig  ][mr + g + 8];
                ah[mi][2] = Ah[kk2+tig+4][mr + g    ];
                ah[mi][3] = Ah[kk2+tig+4][mr + g + 8];
                al[mi][0] = Al[kk2+tig  ][mr + g    ];
                al[mi][1] = Al[kk2+tig  ][mr + g + 8];
                al[mi][2] = Al[kk2+tig+4][mr + g    ];
                al[mi][3] = Al[kk2+tig+4][mr + g + 8];
            }
#pragma unroll
            for (int ni = 0; ni < 4; ni++) {
                uint32_t bh[2], bl[2];
                bh[0] = Bh[kk2+tig  ][wn + ni*8 + g];
                bh[1] = Bh[kk2+tig+4][wn + ni*8 + g];
                bl[0] = Bl[kk2+tig  ][wn + ni*8 + g];
                bl[1] = Bl[kk2+tig+4][wn + ni*8 + g];
#pragma unroll
                for (int mi = 0; mi < 2; mi++) {
                    mma16bf(c[mi][ni], ah[mi], bh);
                    mma16bf(c[mi][ni], ah[mi], bl);
                    mma16bf(c[mi][ni], al[mi], bh);
                }
            }
        }
        __syncthreads();
        if (t < 3) storeT();
        __syncthreads();
    }

    float* Ep = g_E[b];
#pragma unroll
    for (int mi = 0; mi < 2; mi++) {
#pragma unroll
        for (int ni = 0; ni < 4; ni++) {
            int row = row0 + wm + mi * 16 + g;
            int col = col0 + wn + ni * 8 + tig * 2;
            *(float2*)&Ep[row * NPIX + col]       = make_float2(c[mi][ni][0], c[mi][ni][1]);
            *(float2*)&Ep[(row + 8) * NPIX + col] = make_float2(c[mi][ni][2], c[mi][ni][3]);
        }
    }
}

// ---------------- e_space stats (fexp) ----------------
__global__ void k_colpart()
{
    int b = blockIdx.z, ch = blockIdx.y;
    int m = blockIdx.x * 256 + threadIdx.x;
    const float* Ep = g_E[b];
    float mx = -3.0e38f, s = 0.f;
    int n0 = ch * (NPIX / NCHUNK);
    for (int n = n0; n < n0 + NPIX / NCHUNK; n++) {
        float v = Ep[n * NPIX + m];
        if (v > mx) { s = s * fexp(mx - v) + 1.f; mx = v; }
        else        { s += fexp(v - mx); }
    }
    g_pmax[b][ch][m] = mx;
    g_psum[b][ch][m] = s;
}

__global__ void k_colreduce()
{
    int b = blockIdx.y, m = blockIdx.x * 256 + threadIdx.x;
    float mx = -3.0e38f, s = 0.f;
#pragma unroll
    for (int ch = 0; ch < NCHUNK; ch++) {
        float pm = g_pmax[b][ch][m], ps = g_psum[b][ch][m];
        float nm = fmaxf(mx, pm);
        s = s * fexp(mx - nm) + ps * fexp(pm - nm);
        mx = nm;
    }
    g_colmax[b][m] = mx;
    g_colrsum[b][m] = 1.f / s;
}

__global__ void k_rowstats()
{
    int b = blockIdx.y;
    int n = blockIdx.x * 8 + (threadIdx.x >> 5);
    int lane = threadIdx.x & 31;
    const float* row = g_E[b] + n * NPIX;
    float mx = -3.0e38f, s = 0.f;
    for (int m = lane; m < NPIX; m += 32) {
        float v = row[m];
        if (v > mx) { s = s * fexp(mx - v) + 1.f; mx = v; }
        else        { s += fexp(v - mx); }
    }
#pragma unroll
    for (int off = 16; off; off >>= 1) {
        float om = __shfl_xor_sync(0xffffffffu, mx, off);
        float os = __shfl_xor_sync(0xffffffffu, s, off);
        float nm = fmaxf(mx, om);
        s = s * fexp(mx - nm) + os * fexp(om - nm);
        mx = nm;
    }
    if (lane == 0) { g_rowmax[b][n] = mx; g_rowrsum[b][n] = 1.f / s; }
}

// ======================================================================
// k_zgemm_mma (unchanged from R5)
// ======================================================================
__global__ void __launch_bounds__(256) k_zgemm_mma()
{
    int zi = blockIdx.z >> 2, b = blockIdx.z & 3;
    int n0 = blockIdx.x * 64;
    const float* __restrict__ Asrc = zi ? g_A2[b] : g_A1[b];
    const float* __restrict__ Bsrc = g_PRE[zi][b];

    __shared__ uint32_t As[128][36];
    __shared__ uint32_t Bs[32][72];

    int tid = threadIdx.x;
    int wid = tid >> 5, lane = tid & 31;
    int g = lane >> 2, tig = lane & 3;
    int wm = (wid & 3) * 32, wn = (wid >> 2) * 32;

    int am = tid >> 1, ak = (tid & 1) * 16;
    int bkk = tid >> 3, bjq = (tid & 7) * 8;

    float4 sA[4], sB[2];
    float c[2][4][4] = {};

    auto loadT = [&](int k0) {
#pragma unroll
        for (int q = 0; q < 4; q++) sA[q] = *(const float4*)&Asrc[am * CI + k0 + ak + q * 4];
#pragma unroll
        for (int q = 0; q < 2; q++) sB[q] = *(const float4*)&Bsrc[(k0 + bkk) * NPIX + n0 + bjq + q * 4];
    };
    auto storeT = [&]() {
#pragma unroll
        for (int q = 0; q < 4; q++) {
            *(uint4*)&As[am][ak + q * 4] = make_uint4(
                f2t(sA[q].x), f2t(sA[q].y), f2t(sA[q].z), f2t(sA[q].w));
        }
#pragma unroll
        for (int q = 0; q < 2; q++) {
            *(uint4*)&Bs[bkk][bjq + q * 4] = make_uint4(
                f2t(sB[q].x), f2t(sB[q].y), f2t(sB[q].z), f2t(sB[q].w));
        }
    };

    loadT(0); storeT(); __syncthreads();
    for (int t = 0; t < 4; t++) {
        if (t < 3) loadT((t + 1) * 32);
#pragma unroll
        for (int kk = 0; kk < 32; kk += 8) {
            uint32_t a[2][4];
#pragma unroll
            for (int mi = 0; mi < 2; mi++) {
                int mr = wm + mi * 16;
                a[mi][0]=As[mr+g  ][kk+tig  ]; a[mi][1]=As[mr+g+8][kk+tig  ];
                a[mi][2]=As[mr+g  ][kk+tig+4]; a[mi][3]=As[mr+g+8][kk+tig+4];
            }
#pragma unroll
            for (int ni = 0; ni < 4; ni++) {
                uint32_t bb[2];
                bb[0]=Bs[kk+tig  ][wn+ni*8+g];
                bb[1]=Bs[kk+tig+4][wn+ni*8+g];
                mma8(c[0][ni], a[0], bb);
                mma8(c[1][ni], a[1], bb);
            }
        }
        __syncthreads();
        if (t < 3) storeT();
        __syncthreads();
    }

    float* Zout = g_Z[zi][b];
#pragma unroll
    for (int mi = 0; mi < 2; mi++) {
#pragma unroll
        for (int ni = 0; ni < 4; ni++) {
            int row = wm + mi * 16 + g;
            int col = n0 + wn + ni * 8 + tig * 2;
            *(float2*)&Zout[row * NPIX + col]       = make_float2(c[mi][ni][0], c[mi][ni][1]);
            *(float2*)&Zout[(row + 8) * NPIX + col] = make_float2(c[mi][ni][2], c[mi][ni][3]);
        }
    }
}

// ======================================================================
// k_ygemm_mma (R5 structure, fexp in storeT)
// ======================================================================
__global__ void __launch_bounds__(256) k_ygemm_mma()
{
    int yi = blockIdx.z >> 2, b = blockIdx.z & 3;
    int n0 = blockIdx.x * 64;
    const float* __restrict__ Zp = g_Z[yi][b];
    const float* __restrict__ Ep = g_E[b];
    const float* __restrict__ vmax = yi ? g_rowmax[b]  : g_colmax[b];
    const float* __restrict__ vrs  = yi ? g_rowrsum[b] : g_colrsum[b];

    __shared__ uint32_t As[128][36];
    __shared__ uint32_t Bs[2304];
    __shared__ float s_max[64], s_rs[64];

    int tid = threadIdx.x;
    if (tid < 64) { s_max[tid] = vmax[n0 + tid]; s_rs[tid] = vrs[n0 + tid]; }
    __syncthreads();

    int wid = tid >> 5, lane = tid & 31;
    int g = lane >> 2, tig = lane & 3;
    int wm = (wid & 3) * 32, wn = (wid >> 2) * 32;

    int am = tid >> 1, ak = (tid & 1) * 16;
    int bkk = tid >> 3, bjq = (tid & 7) * 8;
    int bj = tid >> 2, bkq = (tid & 3) * 8;

    float4 sA[4], sB[2];
    float c[2][4][4] = {};

    auto loadT = [&](int k0) {
#pragma unroll
        for (int q = 0; q < 4; q++) sA[q] = *(const float4*)&Zp[am * NPIX + k0 + ak + q * 4];
        if (yi == 0) {
#pragma unroll
            for (int q = 0; q < 2; q++)
                sB[q] = *(const float4*)&Ep[(k0 + bkk) * NPIX + n0 + bjq + q * 4];
        } else {
#pragma unroll
            for (int q = 0; q < 2; q++)
                sB[q] = *(const float4*)&Ep[(n0 + bj) * NPIX + k0 + bkq + q * 4];
        }
    };
    auto storeT = [&]() {
#pragma unroll
        for (int q = 0; q < 4; q++) {
            *(uint4*)&As[am][ak + q * 4] = make_uint4(
                f2t(sA[q].x), f2t(sA[q].y), f2t(sA[q].z), f2t(sA[q].w));
        }
        if (yi == 0) {
            uint32_t* brow = &Bs[bkk * 72 + bjq];
#pragma unroll
            for (int q = 0; q < 2; q++) {
                brow[q*4+0] = f2t(fexp(sB[q].x - s_max[bjq + q*4 + 0]));
                brow[q*4+1] = f2t(fexp(sB[q].y - s_max[bjq + q*4 + 1]));
                brow[q*4+2] = f2t(fexp(sB[q].z - s_max[bjq + q*4 + 2]));
                brow[q*4+3] = f2t(fexp(sB[q].w - s_max[bjq + q*4 + 3]));
            }
        } else {
            float mxj = s_max[bj];
            uint32_t* brow = &Bs[bj * 36 + bkq];
#pragma unroll
            for (int q = 0; q < 2; q++) {
                brow[q*4+0] = f2t(fexp(sB[q].x - mxj));
                brow[q*4+1] = f2t(fexp(sB[q].y - mxj));
                brow[q*4+2] = f2t(fexp(sB[q].z - mxj));
                brow[q*4+3] = f2t(fexp(sB[q].w - mxj));
            }
        }
    };

    loadT(0); storeT(); __syncthreads();
    for (int t = 0; t < 72; t++) {
        if (t < 71) loadT((t + 1) * 32);
#pragma unroll
        for (int kk = 0; kk < 32; kk += 8) {
            uint32_t a[2][4];
#pragma unroll
            for (int mi = 0; mi < 2; mi++) {
                int mr = wm + mi * 16;
                a[mi][0]=As[mr+g  ][kk+tig  ]; a[mi][1]=As[mr+g+8][kk+tig  ];
                a[mi][2]=As[mr+g  ][kk+tig+4]; a[mi][3]=As[mr+g+8][kk+tig+4];
            }
#pragma unroll
            for (int ni = 0; ni < 4; ni++) {
                uint32_t bb[2];
                if (yi == 0) {
                    bb[0] = Bs[(kk+tig  ) * 72 + wn + ni*8 + g];
                    bb[1] = Bs[(kk+tig+4) * 72 + wn + ni*8 + g];
                } else {
                    bb[0] = Bs[(wn + ni*8 + g) * 36 + kk + tig    ];
                    bb[1] = Bs[(wn + ni*8 + g) * 36 + kk + tig + 4];
                }
                mma8(c[0][ni], a[0], bb);
                mma8(c[1][ni], a[1], bb);
            }
        }
        __syncthreads();
        if (t < 71) storeT();
        __syncthreads();
    }

    float* Yp = g_Y[yi][b];
#pragma unroll
    for (int mi = 0; mi < 2; mi++) {
#pragma unroll
        for (int ni = 0; ni < 4; ni++) {
            int row = wm + mi * 16 + g;
            int col = wn + ni * 8 + tig * 2;
            float r0 = s_rs[col], r1 = s_rs[col + 1];
            *(float2*)&Yp[row * NPIX + n0 + col] =
                make_float2(c[mi][ni][0] * r0, c[mi][ni][1] * r1);
            *(float2*)&Yp[(row + 8) * NPIX + n0 + col] =
                make_float2(c[mi][ni][2] * r0, c[mi][ni][3] * r1);
        }
    }
}

// ======================================================================
// k_post_mma (unchanged from R5)
// ======================================================================
__global__ void __launch_bounds__(256) k_post_mma(const float* __restrict__ x1,
                                                  const float* __restrict__ x2,
                                                  float* __restrict__ out)
{
    int i = blockIdx.z >> 2, b = blockIdx.z & 3;
    int m0 = blockIdx.y * 128, n0 = blockIdx.x * 64;
    const float* __restrict__ Asrc = g_Wpost[i];
    const float* __restrict__ Bsrc = g_Y[i][b];

    __shared__ uint32_t As[128][36];
    __shared__ uint32_t Bs[32][72];

    int tid = threadIdx.x;
    int wid = tid >> 5, lane = tid & 31;
    int g = lane >> 2, tig = lane & 3;
    int wm = (wid & 3) * 32, wn = (wid >> 2) * 32;

    int am = tid >> 1, ak = (tid & 1) * 16;
    int bkk = tid >> 3, bjq = (tid & 7) * 8;

    float4 sA[4], sB[2];
    float c[2][4][4] = {};

    auto loadT = [&](int k0) {
#pragma unroll
        for (int q = 0; q < 4; q++) sA[q] = *(const float4*)&Asrc[(m0 + am) * CI + k0 + ak + q * 4];
#pragma unroll
        for (int q = 0; q < 2; q++) sB[q] = *(const float4*)&Bsrc[(k0 + bkk) * NPIX + n0 + bjq + q * 4];
    };
    auto storeT = [&]() {
#pragma unroll
        for (int q = 0; q < 4; q++) {
            *(uint4*)&As[am][ak + q * 4] = make_uint4(
                f2t(sA[q].x), f2t(sA[q].y), f2t(sA[q].z), f2t(sA[q].w));
        }
#pragma unroll
        for (int q = 0; q < 2; q++) {
            *(uint4*)&Bs[bkk][bjq + q * 4] = make_uint4(
                f2t(sB[q].x), f2t(sB[q].y), f2t(sB[q].z), f2t(sB[q].w));
        }
    };

    loadT(0); storeT(); __syncthreads();
    for (int t = 0; t < 4; t++) {
        if (t < 3) loadT((t + 1) * 32);
#pragma unroll
        for (int kk = 0; kk < 32; kk += 8) {
            uint32_t a[2][4];
#pragma unroll
            for (int mi = 0; mi < 2; mi++) {
                int mr = wm + mi * 16;
                a[mi][0]=As[mr+g  ][kk+tig  ]; a[mi][1]=As[mr+g+8][kk+tig  ];
                a[mi][2]=As[mr+g  ][kk+tig+4]; a[mi][3]=As[mr+g+8][kk+tig+4];
            }
#pragma unroll
            for (int ni = 0; ni < 4; ni++) {
                uint32_t bb[2];
                bb[0]=Bs[kk+tig  ][wn+ni*8+g];
                bb[1]=Bs[kk+tig+4][wn+ni*8+g];
                mma8(c[0][ni], a[0], bb);
                mma8(c[1][ni], a[1], bb);
            }
        }
        __syncthreads();
        if (t < 3) storeT();
        __syncthreads();
    }

    const float* xs = (i ? x2 : x1) + b * CC * NPIX;
    float* op = out + (size_t)i * BATCH * CC * NPIX + (size_t)b * CC * NPIX;
#pragma unroll
    for (int mi = 0; mi < 2; mi++) {
#pragma unroll
        for (int ni = 0; ni < 4; ni++) {
            int row = m0 + wm + mi * 16 + g;
            int col = n0 + wn + ni * 8 + tig * 2;
            float b0 = g_bpost[i][row], b1 = g_bpost[i][row + 8];
            float2 r0 = *(const float2*)&xs[row * NPIX + col];
            float2 r1 = *(const float2*)&xs[(row + 8) * NPIX + col];
            *(float2*)&op[row * NPIX + col] =
                make_float2(c[mi][ni][0] + b0 + r0.x, c[mi][ni][1] + b0 + r0.y);
            *(float2*)&op[(row + 8) * NPIX + col] =
                make_float2(c[mi][ni][2] + b1 + r1.x, c[mi][ni][3] + b1 + r1.y);
        }
    }
}

// ---------------- launcher ----------------
extern "C" void kernel_launch(void* const* d_in, const int* in_sizes, int n_in,
                              void* d_out, int out_size)
{
    const float* x1      = (const float*)d_in[0];
    const float* x2      = (const float*)d_in[1];
    const float* bn_pre  = (const float*)d_in[2];
    const float* w_pre   = (const float*)d_in[3];
    const float* b_pre   = (const float*)d_in[4];
    const float* w_post  = (const float*)d_in[5];
    const float* b_post  = (const float*)d_in[6];
    const float* bn_post = (const float*)d_in[7];
    float* out = (float*)d_out;

    k_fold<<<2, 512>>>(bn_pre, w_pre, b_pre, w_post, b_post, bn_post);
    k_pre_bf16<<<dim3(36, 1, 16), 256>>>(x1, x2);
    k_etime_bf16<<<dim3(2, ETSPLIT, BATCH), 256>>>();
    k_etreduce<<<dim3(64, BATCH), 256>>>();
    k_softmax_time<<<BATCH, 128>>>();
    k_espace_bf16<<<dim3(36, 18, BATCH), 256>>>();
    k_zgemm_mma<<<dim3(36, 1, 8), 256>>>();
    k_colpart<<<dim3(9, NCHUNK, BATCH), 256>>>();
    k_colreduce<<<dim3(9, BATCH), 256>>>();
    k_rowstats<<<dim3(288, BATCH), 256>>>();
    k_ygemm_mma<<<dim3(36, 1, 8), 256>>>();
    k_post_mma<<<dim3(36, 2, 8), 256>>>(x1, x2, out);
}

// round 8
// speedup vs baseline: 1.2385x; 1.2385x over previous
#include <cuda_runtime.h>
#include <cuda_bf16.h>
#include <math.h>
#include <stdint.h>

#define BATCH 4
#define CC 256
#define CI 128
#define NPIX 2304
#define BNEPS 1e-5f
#define NCHUNK 18
#define ETSPLIT 18

// ---------------- scratch ----------------
__device__ float g_PRE[4][BATCH][CI*NPIX];
__device__ float g_ETpart[BATCH][ETSPLIT][CI*CI];
__device__ float g_ET[BATCH][CI*CI];
__device__ float g_A1[BATCH][CI*CI];
__device__ float g_A2[BATCH][CI*CI];
__device__ float g_E[BATCH][NPIX*NPIX];
__device__ float g_Z[2][BATCH][CI*NPIX];
__device__ float g_Y[2][BATCH][CI*NPIX];
__device__ float g_colmax[BATCH][NPIX];
__device__ float g_colrsum[BATCH][NPIX];
__device__ float g_rowmax[BATCH][NPIX];
__device__ float g_rowrsum[BATCH][NPIX];
__device__ float g_pmax[BATCH][NCHUNK][NPIX];
__device__ float g_psum[BATCH][NCHUNK][NPIX];
__device__ float g_WpreH[4][CI*CC];
__device__ float g_WpreL[4][CI*CC];
__device__ float g_bpre[4][CI];
__device__ float g_Wpost[2][CC*CI];
__device__ float g_bpost[2][CC];

// ---------------- helpers ----------------
__device__ __forceinline__ uint32_t f2t(float x) {
    uint32_t r;
    asm("cvt.rna.tf32.f32 %0, %1;" : "=r"(r) : "f"(x));
    return r;
}
__device__ __forceinline__ void mma8(float c[4], const uint32_t a[4], const uint32_t b[2]) {
    asm volatile(
        "mma.sync.aligned.m16n8k8.row.col.f32.tf32.tf32.f32 "
        "{%0,%1,%2,%3}, {%4,%5,%6,%7}, {%8,%9}, {%0,%1,%2,%3};"
        : "+f"(c[0]), "+f"(c[1]), "+f"(c[2]), "+f"(c[3])
        : "r"(a[0]), "r"(a[1]), "r"(a[2]), "r"(a[3]), "r"(b[0]), "r"(b[1]));
}
__device__ __forceinline__ uint32_t pack_bf(float e, float o) {
    uint32_t r;
    asm("cvt.rn.bf16x2.f32 %0, %1, %2;" : "=r"(r) : "f"(o), "f"(e));
    return r;
}
__device__ __forceinline__ float bf_round(float x) {
    return __bfloat162float(__float2bfloat16(x));
}
__device__ __forceinline__ void mma16bf(float c[4], const uint32_t a[4], const uint32_t b[2]) {
    asm volatile(
        "mma.sync.aligned.m16n8k16.row.col.f32.bf16.bf16.f32 "
        "{%0,%1,%2,%3}, {%4,%5,%6,%7}, {%8,%9}, {%0,%1,%2,%3};"
        : "+f"(c[0]), "+f"(c[1]), "+f"(c[2]), "+f"(c[3])
        : "r"(a[0]), "r"(a[1]), "r"(a[2]), "r"(a[3]), "r"(b[0]), "r"(b[1]));
}
__device__ __forceinline__ void split_pack(float e, float o, uint32_t& hp, uint32_t& lp) {
    float eh = bf_round(e), oh = bf_round(o);
    hp = pack_bf(eh, oh);
    lp = pack_bf(e - eh, o - oh);
}

// ---------------- BN folding ----------------
__global__ void k_fold(const float* __restrict__ bn_pre, const float* __restrict__ w_pre,
                       const float* __restrict__ b_pre, const float* __restrict__ w_post,
                       const float* __restrict__ b_post, const float* __restrict__ bn_post)
{
    int tid = threadIdx.x;
    if (blockIdx.x == 0) {
        int i = tid >> 7, o = tid & 127;
        const float* bp = bn_pre + i * 4 * CC;
        const float* w  = w_pre + (i * CI + o) * CC;
        float acc = b_pre[i * CI + o];
        for (int c = 0; c < CC; c++) {
            float s = bp[c] * rsqrtf(bp[3 * CC + c] + BNEPS);
            float t = bp[CC + c] - bp[2 * CC + c] * s;
            float wv = w[c] * s;
            float h = bf_round(wv);
            g_WpreH[i][o * CC + c] = h;
            g_WpreL[i][o * CC + c] = wv - h;
            acc += w[c] * t;
        }
        g_bpre[i][o] = acc;
    } else {
        int i = tid >> 8, o = tid & 255;
        const float* bp = bn_post + i * 4 * CC;
        float s = bp[o] * rsqrtf(bp[3 * CC + o] + BNEPS);
        const float* w = w_post + (i * CC + o) * CI;
        for (int c = 0; c < CI; c++)
            g_Wpost[i][o * CI + c] = w[c] * s;
        g_bpost[i][o] = b_post[i * CC + o] * s + bp[CC + o] - bp[2 * CC + o] * s;
    }
}

// ======================================================================
// k_pre_bf16 (R5, unchanged): 3-term bf16, pipelined, 128x64
// ======================================================================
__global__ void __launch_bounds__(256) k_pre_bf16(const float* __restrict__ x1,
                                                  const float* __restrict__ x2)
{
    int i = blockIdx.z >> 2, b = blockIdx.z & 3;
    int n0 = blockIdx.x * 64;
    const float* __restrict__ AHf = g_WpreH[i];
    const float* __restrict__ ALf = g_WpreL[i];
    const float* __restrict__ Bsrc = ((i & 1) ? x2 : x1) + b * CC * NPIX;

    __shared__ uint32_t Ah[128][20], Al[128][20], Bh[16][72], Bl[16][72];

    int tid = threadIdx.x;
    int wid = tid >> 5, lane = tid & 31;
    int g = lane >> 2, tig = lane & 3;
    int wm = (wid & 3) * 32, wn = (wid >> 2) * 32;

    int am = tid >> 2, akq = (tid & 3) * 8;
    int bk2 = tid >> 4, bn4 = (tid & 15) * 4;

    float4 sh0[2], sh1[2], sl0[2], sl1[2], sbe, sbo;
    float c[2][4][4] = {};

    auto loadT = [&](int k0) {
#pragma unroll
        for (int it = 0; it < 2; it++) {
            int m = am + it * 64;
            sh0[it] = *(const float4*)&AHf[m * CC + k0 + akq];
            sh1[it] = *(const float4*)&AHf[m * CC + k0 + akq + 4];
            sl0[it] = *(const float4*)&ALf[m * CC + k0 + akq];
            sl1[it] = *(const float4*)&ALf[m * CC + k0 + akq + 4];
        }
        const float* be = &Bsrc[(k0 + 2 * bk2) * NPIX + n0 + bn4];
        sbe = *(const float4*)be;
        sbo = *(const float4*)(be + NPIX);
    };
    auto storeT = [&]() {
#pragma unroll
        for (int it = 0; it < 2; it++) {
            int m = am + it * 64, kq2 = akq >> 1;
            *(uint4*)&Ah[m][kq2] = make_uint4(
                pack_bf(sh0[it].x, sh0[it].y), pack_bf(sh0[it].z, sh0[it].w),
                pack_bf(sh1[it].x, sh1[it].y), pack_bf(sh1[it].z, sh1[it].w));
            *(uint4*)&Al[m][kq2] = make_uint4(
                pack_bf(sl0[it].x, sl0[it].y), pack_bf(sl0[it].z, sl0[it].w),
                pack_bf(sl1[it].x, sl1[it].y), pack_bf(sl1[it].z, sl1[it].w));
        }
        uint32_t h0,l0,h1,l1,h2,l2,h3,l3;
        split_pack(sbe.x, sbo.x, h0, l0); split_pack(sbe.y, sbo.y, h1, l1);
        split_pack(sbe.z, sbo.z, h2, l2); split_pack(sbe.w, sbo.w, h3, l3);
        *(uint4*)&Bh[bk2][bn4] = make_uint4(h0, h1, h2, h3);
        *(uint4*)&Bl[bk2][bn4] = make_uint4(l0, l1, l2, l3);
    };

    loadT(0); storeT(); __syncthreads();
    for (int t = 0; t < 8; t++) {
        if (t < 7) loadT((t + 1) * 32);
#pragma unroll
        for (int kk2 = 0; kk2 < 16; kk2 += 8) {
            uint32_t ah[2][4], al[2][4];
#pragma unroll
            for (int mi = 0; mi < 2; mi++) {
                int mr = wm + mi * 16;
                ah[mi][0]=Ah[mr+g  ][kk2+tig  ]; ah[mi][1]=Ah[mr+g+8][kk2+tig  ];
                ah[mi][2]=Ah[mr+g  ][kk2+tig+4]; ah[mi][3]=Ah[mr+g+8][kk2+tig+4];
                al[mi][0]=Al[mr+g  ][kk2+tig  ]; al[mi][1]=Al[mr+g+8][kk2+tig  ];
                al[mi][2]=Al[mr+g  ][kk2+tig+4]; al[mi][3]=Al[mr+g+8][kk2+tig+4];
            }
#pragma unroll
            for (int ni = 0; ni < 4; ni++) {
                uint32_t bh[2], bl[2];
                bh[0]=Bh[kk2+tig  ][wn+ni*8+g]; bh[1]=Bh[kk2+tig+4][wn+ni*8+g];
                bl[0]=Bl[kk2+tig  ][wn+ni*8+g]; bl[1]=Bl[kk2+tig+4][wn+ni*8+g];
#pragma unroll
                for (int mi = 0; mi < 2; mi++) {
                    mma16bf(c[mi][ni], ah[mi], bh);
                    mma16bf(c[mi][ni], ah[mi], bl);
                    mma16bf(c[mi][ni], al[mi], bh);
                }
            }
        }
        __syncthreads();
        if (t < 7) storeT();
        __syncthreads();
    }

    float* Cout = g_PRE[i][b];
#pragma unroll
    for (int mi = 0; mi < 2; mi++) {
#pragma unroll
        for (int ni = 0; ni < 4; ni++) {
            int row = wm + mi * 16 + g;
            int col = n0 + wn + ni * 8 + tig * 2;
            float b0 = g_bpre[i][row], b1 = g_bpre[i][row + 8];
            *(float2*)&Cout[row * NPIX + col] =
                make_float2(c[mi][ni][0] + b0, c[mi][ni][1] + b0);
            *(float2*)&Cout[(row + 8) * NPIX + col] =
                make_float2(c[mi][ni][2] + b1, c[mi][ni][3] + b1);
        }
    }
}

// ======================================================================
// k_etime_bf16 (R5, unchanged)
// ======================================================================
__global__ void __launch_bounds__(256) k_etime_bf16()
{
    int b = blockIdx.z, ks = blockIdx.y;
    int n0 = blockIdx.x * 64;
    int kbeg = ks * (NPIX / ETSPLIT);
    const float* __restrict__ Tm = g_PRE[2][b];
    const float* __restrict__ Pm = g_PRE[3][b];

    __shared__ uint32_t Ah[128][20], Al[128][20], Bh[64][20], Bl[64][20];

    int tid = threadIdx.x;
    int wid = tid >> 5, lane = tid & 31;
    int g = lane >> 2, tig = lane & 3;
    int wm = (wid & 3) * 32, wn = (wid >> 2) * 32;

    int am = tid >> 1, ak = (tid & 1) * 16;
    int bn = tid >> 2, bk = (tid & 3) * 8;

    float4 sA[4], sB[2];
    float c[2][4][4] = {};

    auto loadT = [&](int k0) {
#pragma unroll
        for (int q = 0; q < 4; q++) sA[q] = *(const float4*)&Tm[am * NPIX + k0 + ak + q * 4];
#pragma unroll
        for (int q = 0; q < 2; q++) sB[q] = *(const float4*)&Pm[(n0 + bn) * NPIX + k0 + bk + q * 4];
    };
    auto storeT = [&]() {
#pragma unroll
        for (int q = 0; q < 4; q++) {
            uint32_t h0,l0,h1,l1;
            split_pack(sA[q].x, sA[q].y, h0, l0);
            split_pack(sA[q].z, sA[q].w, h1, l1);
            int k2 = (ak >> 1) + q * 2;
            Ah[am][k2] = h0; Ah[am][k2+1] = h1;
            Al[am][k2] = l0; Al[am][k2+1] = l1;
        }
#pragma unroll
        for (int q = 0; q < 2; q++) {
            uint32_t h0,l0,h1,l1;
            split_pack(sB[q].x, sB[q].y, h0, l0);
            split_pack(sB[q].z, sB[q].w, h1, l1);
            int k2 = (bk >> 1) + q * 2;
            Bh[bn][k2] = h0; Bh[bn][k2+1] = h1;
            Bl[bn][k2] = l0; Bl[bn][k2+1] = l1;
        }
    };

    loadT(kbeg); storeT(); __syncthreads();
    for (int t = 0; t < 4; t++) {
        if (t < 3) loadT(kbeg + (t + 1) * 32);
#pragma unroll
        for (int kk2 = 0; kk2 < 16; kk2 += 8) {
            uint32_t ah[2][4], al[2][4];
#pragma unroll
            for (int mi = 0; mi < 2; mi++) {
                int mr = wm + mi * 16;
                ah[mi][0]=Ah[mr+g  ][kk2+tig  ]; ah[mi][1]=Ah[mr+g+8][kk2+tig  ];
                ah[mi][2]=Ah[mr+g  ][kk2+tig+4]; ah[mi][3]=Ah[mr+g+8][kk2+tig+4];
                al[mi][0]=Al[mr+g  ][kk2+tig  ]; al[mi][1]=Al[mr+g+8][kk2+tig  ];
                al[mi][2]=Al[mr+g  ][kk2+tig+4]; al[mi][3]=Al[mr+g+8][kk2+tig+4];
            }
#pragma unroll
            for (int ni = 0; ni < 4; ni++) {
                int nr = wn + ni * 8 + g;
                uint32_t bh[2], bl[2];
                bh[0]=Bh[nr][kk2+tig]; bh[1]=Bh[nr][kk2+tig+4];
                bl[0]=Bl[nr][kk2+tig]; bl[1]=Bl[nr][kk2+tig+4];
#pragma unroll
                for (int mi = 0; mi < 2; mi++) {
                    mma16bf(c[mi][ni], ah[mi], bh);
                    mma16bf(c[mi][ni], ah[mi], bl);
                    mma16bf(c[mi][ni], al[mi], bh);
                }
            }
        }
        __syncthreads();
        if (t < 3) storeT();
        __syncthreads();
    }

    float* outp = g_ETpart[b][ks];
#pragma unroll
    for (int mi = 0; mi < 2; mi++) {
#pragma unroll
        for (int ni = 0; ni < 4; ni++) {
            int row = wm + mi * 16 + g;
            int col = n0 + wn + ni * 8 + tig * 2;
            *(float2*)&outp[row * CI + col]       = make_float2(c[mi][ni][0], c[mi][ni][1]);
            *(float2*)&outp[(row + 8) * CI + col] = make_float2(c[mi][ni][2], c[mi][ni][3]);
        }
    }
}

__global__ void k_etreduce()
{
    int b = blockIdx.y, idx = blockIdx.x * 256 + threadIdx.x;
    float s = 0.f;
#pragma unroll
    for (int p = 0; p < ETSPLIT; p++) s += g_ETpart[b][p][idx];
    g_ET[b][idx] = s;
}

__global__ void k_softmax_time()
{
    int b = blockIdx.x, t = threadIdx.x;
    const float* ET = g_ET[b];
    float mx = -3.0e38f;
    for (int d = 0; d < CI; d++) mx = fmaxf(mx, ET[t * CI + d]);
    float s = 0.f;
    for (int d = 0; d < CI; d++) s += __expf(ET[t * CI + d] - mx);
    float rs = 1.f / s;
    for (int d = 0; d < CI; d++) g_A2[b][t * CI + d] = __expf(ET[t * CI + d] - mx) * rs;
    mx = -3.0e38f;
    for (int d = 0; d < CI; d++) mx = fmaxf(mx, ET[d * CI + t]);
    s = 0.f;
    for (int d = 0; d < CI; d++) s += __expf(ET[d * CI + t] - mx);
    rs = 1.f / s;
    for (int d = 0; d < CI; d++) g_A1[b][t * CI + d] = __expf(ET[d * CI + t] - mx) * rs;
}

// ======================================================================
// k_espace_bf16 (R5, unchanged): 3-term bf16, pipelined
// ======================================================================
__global__ void __launch_bounds__(256) k_espace_bf16()
{
    int b = blockIdx.z;
    int row0 = blockIdx.y * 128, col0 = blockIdx.x * 64;
    const float* __restrict__ T = g_PRE[2][b];
    const float* __restrict__ P = g_PRE[3][b];

    __shared__ uint32_t Ah[16][136], Al[16][136];
    __shared__ uint32_t Bh[16][72],  Bl[16][72];

    int tid = threadIdx.x;
    int wid = tid >> 5, lane = tid & 31;
    int g = lane >> 2, tig = lane & 3;
    int wm = (wid & 3) * 32, wn = (wid >> 2) * 32;

    int ak2 = tid >> 5, an4 = (tid & 31) * 4;
    int bk2 = tid >> 4, bm4 = (tid & 15) * 4;

    float4 sAe[2], sAo[2], sBe, sBo;
    float c[2][4][4] = {};

    auto loadT = [&](int k0) {
#pragma unroll
        for (int it = 0; it < 2; it++) {
            const float* te = &T[(k0 + 2 * (ak2 + it * 8)) * NPIX + row0 + an4];
            sAe[it] = *(const float4*)te;
            sAo[it] = *(const float4*)(te + NPIX);
        }
        const float* pe = &P[(k0 + 2 * bk2) * NPIX + col0 + bm4];
        sBe = *(const float4*)pe;
        sBo = *(const float4*)(pe + NPIX);
    };
    auto storeT = [&]() {
#pragma unroll
        for (int it = 0; it < 2; it++) {
            uint32_t h0,l0,h1,l1,h2,l2,h3,l3;
            split_pack(sAe[it].x, sAo[it].x, h0, l0); split_pack(sAe[it].y, sAo[it].y, h1, l1);
            split_pack(sAe[it].z, sAo[it].z, h2, l2); split_pack(sAe[it].w, sAo[it].w, h3, l3);
            int r = ak2 + it * 8;
            *(uint4*)&Ah[r][an4] = make_uint4(h0, h1, h2, h3);
            *(uint4*)&Al[r][an4] = make_uint4(l0, l1, l2, l3);
        }
        uint32_t h0,l0,h1,l1,h2,l2,h3,l3;
        split_pack(sBe.x, sBo.x, h0, l0); split_pack(sBe.y, sBo.y, h1, l1);
        split_pack(sBe.z, sBo.z, h2, l2); split_pack(sBe.w, sBo.w, h3, l3);
        *(uint4*)&Bh[bk2][bm4] = make_uint4(h0, h1, h2, h3);
        *(uint4*)&Bl[bk2][bm4] = make_uint4(l0, l1, l2, l3);
    };

    loadT(0); storeT(); __syncthreads();
    for (int t = 0; t < 4; t++) {
        if (t < 3) loadT((t + 1) * 32);
#pragma unroll
        for (int kk2 = 0; kk2 < 16; kk2 += 8) {
            uint32_t ah[2][4], al[2][4];
#pragma unroll
            for (int mi = 0; mi < 2; mi++) {
                int mr = wm + mi * 16;
                ah[mi][0] = Ah[kk2+tig  ][mr + g    ];
                ah[mi][1] = Ah[kk2+tig  ][mr + g + 8];
                ah[mi][2] = Ah[kk2+tig+4][mr + g    ];
                ah[mi][3] = Ah[kk2+tig+4][mr + g + 8];
                al[mi][0] = Al[kk2+tig  ][mr + g    ];
                al[mi][1] = Al[kk2+tig  ][mr + g + 8];
                al[mi][2] = Al[kk2+tig+4][mr + g    ];
                al[mi][3] = Al[kk2+tig+4][mr + g + 8];
            }
#pragma unroll
            for (int ni = 0; ni < 4; ni++) {
                uint32_t bh[2], bl[2];
                bh[0] = Bh[kk2+tig  ][wn + ni*8 + g];
                bh[1] = Bh[kk2+tig+4][wn + ni*8 + g];
                bl[0] = Bl[kk2+tig  ][wn + ni*8 + g];
                bl[1] = Bl[kk2+tig+4][wn + ni*8 + g];
#pragma unroll
                for (int mi = 0; mi < 2; mi++) {
                    mma16bf(c[mi][ni], ah[mi], bh);
                    mma16bf(c[mi][ni], ah[mi], bl);
                    mma16bf(c[mi][ni], al[mi], bh);
                }
            }
        }
        __syncthreads();
        if (t < 3) storeT();
        __syncthreads();
    }

    float* Ep = g_E[b];
#pragma unroll
    for (int mi = 0; mi < 2; mi++) {
#pragma unroll
        for (int ni = 0; ni < 4; ni++) {
            int row = row0 + wm + mi * 16 + g;
            int col = col0 + wn + ni * 8 + tig * 2;
            *(float2*)&Ep[row * NPIX + col]       = make_float2(c[mi][ni][0], c[mi][ni][1]);
            *(float2*)&Ep[(row + 8) * NPIX + col] = make_float2(c[mi][ni][2], c[mi][ni][3]);
        }
    }
}

// ---------------- e_space stats (R5, __expf) ----------------
__global__ void k_colpart()
{
    int b = blockIdx.z, ch = blockIdx.y;
    int m = blockIdx.x * 256 + threadIdx.x;
    const float* Ep = g_E[b];
    float mx = -3.0e38f, s = 0.f;
    int n0 = ch * (NPIX / NCHUNK);
    for (int n = n0; n < n0 + NPIX / NCHUNK; n++) {
        float v = Ep[n * NPIX + m];
        if (v > mx) { s = s * __expf(mx - v) + 1.f; mx = v; }
        else        { s += __expf(v - mx); }
    }
    g_pmax[b][ch][m] = mx;
    g_psum[b][ch][m] = s;
}

__global__ void k_colreduce()
{
    int b = blockIdx.y, m = blockIdx.x * 256 + threadIdx.x;
    float mx = -3.0e38f, s = 0.f;
#pragma unroll
    for (int ch = 0; ch < NCHUNK; ch++) {
        float pm = g_pmax[b][ch][m], ps = g_psum[b][ch][m];
        float nm = fmaxf(mx, pm);
        s = s * __expf(mx - nm) + ps * __expf(pm - nm);
        mx = nm;
    }
    g_colmax[b][m] = mx;
    g_colrsum[b][m] = 1.f / s;
}

__global__ void k_rowstats()
{
    int b = blockIdx.y;
    int n = blockIdx.x * 8 + (threadIdx.x >> 5);
    int lane = threadIdx.x & 31;
    const float* row = g_E[b] + n * NPIX;
    float mx = -3.0e38f, s = 0.f;
    for (int m = lane; m < NPIX; m += 32) {
        float v = row[m];
        if (v > mx) { s = s * __expf(mx - v) + 1.f; mx = v; }
        else        { s += __expf(v - mx); }
    }
#pragma unroll
    for (int off = 16; off; off >>= 1) {
        float om = __shfl_xor_sync(0xffffffffu, mx, off);
        float os = __shfl_xor_sync(0xffffffffu, s, off);
        float nm = fmaxf(mx, om);
        s = s * __expf(mx - nm) + os * __expf(om - nm);
        mx = nm;
    }
    if (lane == 0) { g_rowmax[b][n] = mx; g_rowrsum[b][n] = 1.f / s; }
}

// ======================================================================
// k_zgemm_bf16: Z = A@G, SINGLE-PASS bf16 (post-softmax data).
// 128x64 tile, 256 thr, K=128, chunk 32, pipelined.
// A packed [m][k2] stride 20; B packed [k2][n] stride 72.
// ======================================================================
__global__ void __launch_bounds__(256) k_zgemm_bf16()
{
    int zi = blockIdx.z >> 2, b = blockIdx.z & 3;
    int n0 = blockIdx.x * 64;
    const float* __restrict__ Asrc = zi ? g_A2[b] : g_A1[b];
    const float* __restrict__ Bsrc = g_PRE[zi][b];

    __shared__ uint32_t A2[128][20];
    __shared__ uint32_t B2[16][72];

    int tid = threadIdx.x;
    int wid = tid >> 5, lane = tid & 31;
    int g = lane >> 2, tig = lane & 3;
    int wm = (wid & 3) * 32, wn = (wid >> 2) * 32;

    int am = tid >> 1, aks = (tid & 1) * 16;
    int bk2g = tid >> 4, bn4 = (tid & 15) * 4;

    float4 sA[4], sBe, sBo;
    float c[2][4][4] = {};

    auto loadT = [&](int k0) {
#pragma unroll
        for (int q = 0; q < 4; q++) sA[q] = *(const float4*)&Asrc[am * CI + k0 + aks + q * 4];
        const float* be = &Bsrc[(k0 + 2 * bk2g) * NPIX + n0 + bn4];
        sBe = *(const float4*)be;
        sBo = *(const float4*)(be + NPIX);
    };
    auto storeT = [&]() {
        int k2b = aks >> 1;
#pragma unroll
        for (int q = 0; q < 4; q++) {
            A2[am][k2b + q * 2    ] = pack_bf(sA[q].x, sA[q].y);
            A2[am][k2b + q * 2 + 1] = pack_bf(sA[q].z, sA[q].w);
        }
        *(uint4*)&B2[bk2g][bn4] = make_uint4(
            pack_bf(sBe.x, sBo.x), pack_bf(sBe.y, sBo.y),
            pack_bf(sBe.z, sBo.z), pack_bf(sBe.w, sBo.w));
    };

    loadT(0); storeT(); __syncthreads();
    for (int t = 0; t < 4; t++) {
        if (t < 3) loadT((t + 1) * 32);
#pragma unroll
        for (int kk2 = 0; kk2 < 16; kk2 += 8) {
            uint32_t a[2][4];
#pragma unroll
            for (int mi = 0; mi < 2; mi++) {
                int mr = wm + mi * 16;
                a[mi][0]=A2[mr+g  ][kk2+tig  ]; a[mi][1]=A2[mr+g+8][kk2+tig  ];
                a[mi][2]=A2[mr+g  ][kk2+tig+4]; a[mi][3]=A2[mr+g+8][kk2+tig+4];
            }
#pragma unroll
            for (int ni = 0; ni < 4; ni++) {
                uint32_t bb[2];
                bb[0]=B2[kk2+tig  ][wn+ni*8+g];
                bb[1]=B2[kk2+tig+4][wn+ni*8+g];
                mma16bf(c[0][ni], a[0], bb);
                mma16bf(c[1][ni], a[1], bb);
            }
        }
        __syncthreads();
        if (t < 3) storeT();
        __syncthreads();
    }

    float* Zout = g_Z[zi][b];
#pragma unroll
    for (int mi = 0; mi < 2; mi++) {
#pragma unroll
        for (int ni = 0; ni < 4; ni++) {
            int row = wm + mi * 16 + g;
            int col = n0 + wn + ni * 8 + tig * 2;
            *(float2*)&Zout[row * NPIX + col]       = make_float2(c[mi][ni][0], c[mi][ni][1]);
            *(float2*)&Zout[(row + 8) * NPIX + col] = make_float2(c[mi][ni][2], c[mi][ni][3]);
        }
    }
}

// ======================================================================
// k_ygemm_bf16: y = Z @ softmaxed(E), SINGLE-PASS bf16, fused exp.
// 128x64 tile, 256 thr, K=2304, chunk 32 (72 iters), pipelined.
// A (Z) packed [m][k2] stride 20.
// B: yi=0 -> packed [k2][n] stride 72 (rows of E are k-major);
//    yi=1 -> packed [n][k2] stride 20 (rows of E are n-major).
// ======================================================================
__global__ void __launch_bounds__(256) k_ygemm_bf16()
{
    int yi = blockIdx.z >> 2, b = blockIdx.z & 3;
    int n0 = blockIdx.x * 64;
    const float* __restrict__ Zp = g_Z[yi][b];
    const float* __restrict__ Ep = g_E[b];
    const float* __restrict__ vmax = yi ? g_rowmax[b]  : g_colmax[b];
    const float* __restrict__ vrs  = yi ? g_rowrsum[b] : g_colrsum[b];

    __shared__ uint32_t A2[128][20];
    __shared__ uint32_t Bs[1280];   // yi=0: [16][72]=1152; yi=1: [64][20]=1280
    __shared__ float s_max[64], s_rs[64];

    int tid = threadIdx.x;
    if (tid < 64) { s_max[tid] = vmax[n0 + tid]; s_rs[tid] = vrs[n0 + tid]; }
    __syncthreads();

    int wid = tid >> 5, lane = tid & 31;
    int g = lane >> 2, tig = lane & 3;
    int wm = (wid & 3) * 32, wn = (wid >> 2) * 32;

    int am = tid >> 1, aks = (tid & 1) * 16;
    int bk2g = tid >> 4, bn4 = (tid & 15) * 4;   // yi=0
    int bj = tid >> 2, bkq = (tid & 3) * 8;      // yi=1

    float4 sA[4], sB0, sB1;
    float c[2][4][4] = {};

    auto loadT = [&](int k0) {
#pragma unroll
        for (int q = 0; q < 4; q++) sA[q] = *(const float4*)&Zp[am * NPIX + k0 + aks + q * 4];
        if (yi == 0) {
            const float* be = &Ep[(size_t)(k0 + 2 * bk2g) * NPIX + n0 + bn4];
            sB0 = *(const float4*)be;          // even k row
            sB1 = *(const float4*)(be + NPIX); // odd k row
        } else {
            const float* be = &Ep[(size_t)(n0 + bj) * NPIX + k0 + bkq];
            sB0 = *(const float4*)be;
            sB1 = *(const float4*)(be + 4);
        }
    };
    auto storeT = [&]() {
        int k2b = aks >> 1;
#pragma unroll
        for (int q = 0; q < 4; q++) {
            A2[am][k2b + q * 2    ] = pack_bf(sA[q].x, sA[q].y);
            A2[am][k2b + q * 2 + 1] = pack_bf(sA[q].z, sA[q].w);
        }
        if (yi == 0) {
            float m0v = s_max[bn4], m1v = s_max[bn4+1], m2v = s_max[bn4+2], m3v = s_max[bn4+3];
            *(uint4*)&Bs[bk2g * 72 + bn4] = make_uint4(
                pack_bf(__expf(sB0.x - m0v), __expf(sB1.x - m0v)),
                pack_bf(__expf(sB0.y - m1v), __expf(sB1.y - m1v)),
                pack_bf(__expf(sB0.z - m2v), __expf(sB1.z - m2v)),
                pack_bf(__expf(sB0.w - m3v), __expf(sB1.w - m3v)));
        } else {
            float mx = s_max[bj];
            *(uint4*)&Bs[bj * 20 + (bkq >> 1)] = make_uint4(
                pack_bf(__expf(sB0.x - mx), __expf(sB0.y - mx)),
                pack_bf(__expf(sB0.z - mx), __expf(sB0.w - mx)),
                pack_bf(__expf(sB1.x - mx), __expf(sB1.y - mx)),
                pack_bf(__expf(sB1.z - mx), __expf(sB1.w - mx)));
        }
    };

    loadT(0); storeT(); __syncthreads();
    for (int t = 0; t < 72; t++) {
        if (t < 71) loadT((t + 1) * 32);
#pragma unroll
        for (int kk2 = 0; kk2 < 16; kk2 += 8) {
            uint32_t a[2][4];
#pragma unroll
            for (int mi = 0; mi < 2; mi++) {
                int mr = wm + mi * 16;
                a[mi][0]=A2[mr+g  ][kk2+tig  ]; a[mi][1]=A2[mr+g+8][kk2+tig  ];
                a[mi][2]=A2[mr+g  ][kk2+tig+4]; a[mi][3]=A2[mr+g+8][kk2+tig+4];
            }
#pragma unroll
            for (int ni = 0; ni < 4; ni++) {
                uint32_t bb[2];
                if (yi == 0) {
                    bb[0] = Bs[(kk2+tig  ) * 72 + wn + ni*8 + g];
                    bb[1] = Bs[(kk2+tig+4) * 72 + wn + ni*8 + g];
                } else {
                    int nr = wn + ni * 8 + g;
                    bb[0] = Bs[nr * 20 + kk2 + tig    ];
                    bb[1] = Bs[nr * 20 + kk2 + tig + 4];
                }
                mma16bf(c[0][ni], a[0], bb);
                mma16bf(c[1][ni], a[1], bb);
            }
        }
        __syncthreads();
        if (t < 71) storeT();
        __syncthreads();
    }

    float* Yp = g_Y[yi][b];
#pragma unroll
    for (int mi = 0; mi < 2; mi++) {
#pragma unroll
        for (int ni = 0; ni < 4; ni++) {
            int row = wm + mi * 16 + g;
            int col = wn + ni * 8 + tig * 2;
            float r0 = s_rs[col], r1 = s_rs[col + 1];
            *(float2*)&Yp[row * NPIX + n0 + col] =
                make_float2(c[mi][ni][0] * r0, c[mi][ni][1] * r1);
            *(float2*)&Yp[(row + 8) * NPIX + n0 + col] =
                make_float2(c[mi][ni][2] * r0, c[mi][ni][3] * r1);
        }
    }
}

// ======================================================================
// k_post_mma (R5, unchanged tf32)
// ======================================================================
__global__ void __launch_bounds__(256) k_post_mma(const float* __restrict__ x1,
                                                  const float* __restrict__ x2,
                                                  float* __restrict__ out)
{
    int i = blockIdx.z >> 2, b = blockIdx.z & 3;
    int m0 = blockIdx.y * 128, n0 = blockIdx.x * 64;
    const float* __restrict__ Asrc = g_Wpost[i];
    const float* __restrict__ Bsrc = g_Y[i][b];

    __shared__ uint32_t As[128][36];
    __shared__ uint32_t Bs[32][72];

    int tid = threadIdx.x;
    int wid = tid >> 5, lane = tid & 31;
    int g = lane >> 2, tig = lane & 3;
    int wm = (wid & 3) * 32, wn = (wid >> 2) * 32;

    int am = tid >> 1, ak = (tid & 1) * 16;
    int bkk = tid >> 3, bjq = (tid & 7) * 8;

    float4 sA[4], sB[2];
    float c[2][4][4] = {};

    auto loadT = [&](int k0) {
#pragma unroll
        for (int q = 0; q < 4; q++) sA[q] = *(const float4*)&Asrc[(m0 + am) * CI + k0 + ak + q * 4];
#pragma unroll
        for (int q = 0; q < 2; q++) sB[q] = *(const float4*)&Bsrc[(k0 + bkk) * NPIX + n0 + bjq + q * 4];
    };
    auto storeT = [&]() {
#pragma unroll
        for (int q = 0; q < 4; q++) {
            *(uint4*)&As[am][ak + q * 4] = make_uint4(
                f2t(sA[q].x), f2t(sA[q].y), f2t(sA[q].z), f2t(sA[q].w));
        }
#pragma unroll
        for (int q = 0; q < 2; q++) {
            *(uint4*)&Bs[bkk][bjq + q * 4] = make_uint4(
                f2t(sB[q].x), f2t(sB[q].y), f2t(sB[q].z), f2t(sB[q].w));
        }
    };

    loadT(0); storeT(); __syncthreads();
    for (int t = 0; t < 4; t++) {
        if (t < 3) loadT((t + 1) * 32);
#pragma unroll
        for (int kk = 0; kk < 32; kk += 8) {
            uint32_t a[2][4];
#pragma unroll
            for (int mi = 0; mi < 2; mi++) {
                int mr = wm + mi * 16;
                a[mi][0]=As[mr+g  ][kk+tig  ]; a[mi][1]=As[mr+g+8][kk+tig  ];
                a[mi][2]=As[mr+g  ][kk+tig+4]; a[mi][3]=As[mr+g+8][kk+tig+4];
            }
#pragma unroll
            for (int ni = 0; ni < 4; ni++) {
                uint32_t bb[2];
                bb[0]=Bs[kk+tig  ][wn+ni*8+g];
                bb[1]=Bs[kk+tig+4][wn+ni*8+g];
                mma8(c[0][ni], a[0], bb);
                mma8(c[1][ni], a[1], bb);
            }
        }
        __syncthreads();
        if (t < 3) storeT();
        __syncthreads();
    }

    const float* xs = (i ? x2 : x1) + b * CC * NPIX;
    float* op = out + (size_t)i * BATCH * CC * NPIX + (size_t)b * CC * NPIX;
#pragma unroll
    for (int mi = 0; mi < 2; mi++) {
#pragma unroll
        for (int ni = 0; ni < 4; ni++) {
            int row = m0 + wm + mi * 16 + g;
            int col = n0 + wn + ni * 8 + tig * 2;
            float b0 = g_bpost[i][row], b1 = g_bpost[i][row + 8];
            float2 r0 = *(const float2*)&xs[row * NPIX + col];
            float2 r1 = *(const float2*)&xs[(row + 8) * NPIX + col];
            *(float2*)&op[row * NPIX + col] =
                make_float2(c[mi][ni][0] + b0 + r0.x, c[mi][ni][1] + b0 + r0.y);
            *(float2*)&op[(row + 8) * NPIX + col] =
                make_float2(c[mi][ni][2] + b1 + r1.x, c[mi][ni][3] + b1 + r1.y);
        }
    }
}

// ---------------- launcher ----------------
extern "C" void kernel_launch(void* const* d_in, const int* in_sizes, int n_in,
                              void* d_out, int out_size)
{
    const float* x1      = (const float*)d_in[0];
    const float* x2      = (const float*)d_in[1];
    const float* bn_pre  = (const float*)d_in[2];
    const float* w_pre   = (const float*)d_in[3];
    const float* b_pre   = (const float*)d_in[4];
    const float* w_post  = (const float*)d_in[5];
    const float* b_post  = (const float*)d_in[6];
    const float* bn_post = (const float*)d_in[7];
    float* out = (float*)d_out;

    k_fold<<<2, 512>>>(bn_pre, w_pre, b_pre, w_post, b_post, bn_post);
    k_pre_bf16<<<dim3(36, 1, 16), 256>>>(x1, x2);
    k_etime_bf16<<<dim3(2, ETSPLIT, BATCH), 256>>>();
    k_etreduce<<<dim3(64, BATCH), 256>>>();
    k_softmax_time<<<BATCH, 128>>>();
    k_espace_bf16<<<dim3(36, 18, BATCH), 256>>>();
    k_zgemm_bf16<<<dim3(36, 1, 8), 256>>>();
    k_colpart<<<dim3(9, NCHUNK, BATCH), 256>>>();
    k_colreduce<<<dim3(9, BATCH), 256>>>();
    k_rowstats<<<dim3(288, BATCH), 256>>>();
    k_ygemm_bf16<<<dim3(36, 1, 8), 256>>>();
    k_post_mma<<<dim3(36, 2, 8), 256>>>(x1, x2, out);
}

// round 9
// speedup vs baseline: 2.0967x; 1.6929x over previous
#include <cuda_runtime.h>
#include <cuda_bf16.h>
#include <math.h>
#include <stdint.h>

#define BATCH 4
#define CC 256
#define CI 128
#define NPIX 2304
#define BNEPS 1e-5f
#define NCHUNK 18
#define ETSPLIT 18

// ---------------- scratch ----------------
__device__ float g_PRE[4][BATCH][CI*NPIX];
__device__ float g_ETpart[BATCH][ETSPLIT][CI*CI];
__device__ float g_A1[BATCH][CI*CI];
__device__ float g_A2[BATCH][CI*CI];
__device__ float g_E[BATCH][NPIX*NPIX];
__device__ float g_Z[2][BATCH][CI*NPIX];
__device__ float g_Y[2][BATCH][CI*NPIX];
__device__ float g_colmax[BATCH][NPIX];
__device__ float g_colrsum[BATCH][NPIX];
__device__ float g_rowmax[BATCH][NPIX];
__device__ float g_rowrsum[BATCH][NPIX];
__device__ float g_pmax[BATCH][NCHUNK][NPIX];
__device__ float g_psum[BATCH][NCHUNK][NPIX];
__device__ float g_WpreH[4][CI*CC];
__device__ float g_WpreL[4][CI*CC];
__device__ float g_bpre[4][CI];
__device__ float g_Wpost[2][CC*CI];
__device__ float g_bpost[2][CC];

// ---------------- helpers ----------------
__device__ __forceinline__ uint32_t f2t(float x) {
    uint32_t r;
    asm("cvt.rna.tf32.f32 %0, %1;" : "=r"(r) : "f"(x));
    return r;
}
__device__ __forceinline__ void mma8(float c[4], const uint32_t a[4], const uint32_t b[2]) {
    asm volatile(
        "mma.sync.aligned.m16n8k8.row.col.f32.tf32.tf32.f32 "
        "{%0,%1,%2,%3}, {%4,%5,%6,%7}, {%8,%9}, {%0,%1,%2,%3};"
        : "+f"(c[0]), "+f"(c[1]), "+f"(c[2]), "+f"(c[3])
        : "r"(a[0]), "r"(a[1]), "r"(a[2]), "r"(a[3]), "r"(b[0]), "r"(b[1]));
}
__device__ __forceinline__ uint32_t pack_bf(float e, float o) {
    uint32_t r;
    asm("cvt.rn.bf16x2.f32 %0, %1, %2;" : "=r"(r) : "f"(o), "f"(e));
    return r;
}
__device__ __forceinline__ float bf_round(float x) {
    return __bfloat162float(__float2bfloat16(x));
}
__device__ __forceinline__ void mma16bf(float c[4], const uint32_t a[4], const uint32_t b[2]) {
    asm volatile(
        "mma.sync.aligned.m16n8k16.row.col.f32.bf16.bf16.f32 "
        "{%0,%1,%2,%3}, {%4,%5,%6,%7}, {%8,%9}, {%0,%1,%2,%3};"
        : "+f"(c[0]), "+f"(c[1]), "+f"(c[2]), "+f"(c[3])
        : "r"(a[0]), "r"(a[1]), "r"(a[2]), "r"(a[3]), "r"(b[0]), "r"(b[1]));
}
__device__ __forceinline__ void split_pack(float e, float o, uint32_t& hp, uint32_t& lp) {
    float eh = bf_round(e), oh = bf_round(o);
    hp = pack_bf(eh, oh);
    lp = pack_bf(e - eh, o - oh);
}

// ======================================================================
// k_fold: warp-per-output-row, coalesced, shuffle reduce. 128 blocks.
// ======================================================================
__global__ void __launch_bounds__(256) k_fold(
    const float* __restrict__ bn_pre, const float* __restrict__ w_pre,
    const float* __restrict__ b_pre, const float* __restrict__ w_post,
    const float* __restrict__ b_post, const float* __restrict__ bn_post)
{
    int w = blockIdx.x * 8 + (threadIdx.x >> 5);
    int lane = threadIdx.x & 31;
    if (w < 512) {
        int i = w >> 7, o = w & 127;
        const float* bp = bn_pre + i * 4 * CC;
        const float* wr = w_pre + (i * CI + o) * CC;
        float acc = 0.f;
        for (int c = lane; c < CC; c += 32) {
            float s = bp[c] * rsqrtf(bp[3 * CC + c] + BNEPS);
            float t = bp[CC + c] - bp[2 * CC + c] * s;
            float wv = wr[c] * s;
            float h = bf_round(wv);
            g_WpreH[i][o * CC + c] = h;
            g_WpreL[i][o * CC + c] = wv - h;
            acc = fmaf(wr[c], t, acc);
        }
#pragma unroll
        for (int off = 16; off; off >>= 1) acc += __shfl_xor_sync(0xffffffffu, acc, off);
        if (lane == 0) g_bpre[i][o] = acc + b_pre[i * CI + o];
    } else {
        int w2 = w - 512;
        int i = w2 >> 8, o = w2 & 255;
        const float* bp = bn_post + i * 4 * CC;
        float s = bp[o] * rsqrtf(bp[3 * CC + o] + BNEPS);
        const float* wr = w_post + (i * CC + o) * CI;
        for (int c = lane; c < CI; c += 32)
            g_Wpost[i][o * CI + c] = wr[c] * s;
        if (lane == 0)
            g_bpost[i][o] = b_post[i * CC + o] * s + bp[CC + o] - bp[2 * CC + o] * s;
    }
}

// ======================================================================
// pre body (3-term bf16, pipelined, 128x64): pool carve
// Ah[128][20]=2560, Al+2560, Bh[16][72]+5120, Bl+6272 -> 7424 words
// ======================================================================
__device__ __forceinline__ void pre_body(uint32_t* pool, int i, int b, int n0,
                                         const float* __restrict__ x1,
                                         const float* __restrict__ x2)
{
    uint32_t* Ah = pool;
    uint32_t* Al = pool + 2560;
    uint32_t* Bh = pool + 5120;
    uint32_t* Bl = pool + 6272;
    const float* __restrict__ AHf = g_WpreH[i];
    const float* __restrict__ ALf = g_WpreL[i];
    const float* __restrict__ Bsrc = ((i & 1) ? x2 : x1) + b * CC * NPIX;

    int tid = threadIdx.x;
    int wid = tid >> 5, lane = tid & 31;
    int g = lane >> 2, tig = lane & 3;
    int wm = (wid & 3) * 32, wn = (wid >> 2) * 32;

    int am = tid >> 2, akq = (tid & 3) * 8;
    int bk2 = tid >> 4, bn4 = (tid & 15) * 4;

    float4 sh0[2], sh1[2], sl0[2], sl1[2], sbe, sbo;
    float c[2][4][4] = {};

    auto loadT = [&](int k0) {
#pragma unroll
        for (int it = 0; it < 2; it++) {
            int m = am + it * 64;
            sh0[it] = *(const float4*)&AHf[m * CC + k0 + akq];
            sh1[it] = *(const float4*)&AHf[m * CC + k0 + akq + 4];
            sl0[it] = *(const float4*)&ALf[m * CC + k0 + akq];
            sl1[it] = *(const float4*)&ALf[m * CC + k0 + akq + 4];
        }
        const float* be = &Bsrc[(k0 + 2 * bk2) * NPIX + n0 + bn4];
        sbe = *(const float4*)be;
        sbo = *(const float4*)(be + NPIX);
    };
    auto storeT = [&]() {
#pragma unroll
        for (int it = 0; it < 2; it++) {
            int m = am + it * 64, kq2 = akq >> 1;
            *(uint4*)&Ah[m * 20 + kq2] = make_uint4(
                pack_bf(sh0[it].x, sh0[it].y), pack_bf(sh0[it].z, sh0[it].w),
                pack_bf(sh1[it].x, sh1[it].y), pack_bf(sh1[it].z, sh1[it].w));
            *(uint4*)&Al[m * 20 + kq2] = make_uint4(
                pack_bf(sl0[it].x, sl0[it].y), pack_bf(sl0[it].z, sl0[it].w),
                pack_bf(sl1[it].x, sl1[it].y), pack_bf(sl1[it].z, sl1[it].w));
        }
        uint32_t h0,l0,h1,l1,h2,l2,h3,l3;
        split_pack(sbe.x, sbo.x, h0, l0); split_pack(sbe.y, sbo.y, h1, l1);
        split_pack(sbe.z, sbo.z, h2, l2); split_pack(sbe.w, sbo.w, h3, l3);
        *(uint4*)&Bh[bk2 * 72 + bn4] = make_uint4(h0, h1, h2, h3);
        *(uint4*)&Bl[bk2 * 72 + bn4] = make_uint4(l0, l1, l2, l3);
    };

    loadT(0); storeT(); __syncthreads();
    for (int t = 0; t < 8; t++) {
        if (t < 7) loadT((t + 1) * 32);
#pragma unroll
        for (int kk2 = 0; kk2 < 16; kk2 += 8) {
            uint32_t ah[2][4], al[2][4];
#pragma unroll
            for (int mi = 0; mi < 2; mi++) {
                int mr = wm + mi * 16;
                ah[mi][0]=Ah[(mr+g  )*20+kk2+tig  ]; ah[mi][1]=Ah[(mr+g+8)*20+kk2+tig  ];
                ah[mi][2]=Ah[(mr+g  )*20+kk2+tig+4]; ah[mi][3]=Ah[(mr+g+8)*20+kk2+tig+4];
                al[mi][0]=Al[(mr+g  )*20+kk2+tig  ]; al[mi][1]=Al[(mr+g+8)*20+kk2+tig  ];
                al[mi][2]=Al[(mr+g  )*20+kk2+tig+4]; al[mi][3]=Al[(mr+g+8)*20+kk2+tig+4];
            }
#pragma unroll
            for (int ni = 0; ni < 4; ni++) {
                uint32_t bh[2], bl[2];
                bh[0]=Bh[(kk2+tig  )*72+wn+ni*8+g]; bh[1]=Bh[(kk2+tig+4)*72+wn+ni*8+g];
                bl[0]=Bl[(kk2+tig  )*72+wn+ni*8+g]; bl[1]=Bl[(kk2+tig+4)*72+wn+ni*8+g];
#pragma unroll
                for (int mi = 0; mi < 2; mi++) {
                    mma16bf(c[mi][ni], ah[mi], bh);
                    mma16bf(c[mi][ni], ah[mi], bl);
                    mma16bf(c[mi][ni], al[mi], bh);
                }
            }
        }
        __syncthreads();
        if (t < 7) storeT();
        __syncthreads();
    }

    float* Cout = g_PRE[i][b];
#pragma unroll
    for (int mi = 0; mi < 2; mi++) {
#pragma unroll
        for (int ni = 0; ni < 4; ni++) {
            int row = wm + mi * 16 + g;
            int col = n0 + wn + ni * 8 + tig * 2;
            float b0 = g_bpre[i][row], b1 = g_bpre[i][row + 8];
            *(float2*)&Cout[row * NPIX + col] =
                make_float2(c[mi][ni][0] + b0, c[mi][ni][1] + b0);
            *(float2*)&Cout[(row + 8) * NPIX + col] =
                make_float2(c[mi][ni][2] + b1, c[mi][ni][3] + b1);
        }
    }
}

__global__ void __launch_bounds__(256) k_pre23(const float* __restrict__ x1,
                                               const float* __restrict__ x2)
{
    __shared__ uint32_t pool[7424];
    int i = 2 + (blockIdx.z >> 2), b = blockIdx.z & 3;
    pre_body(pool, i, b, blockIdx.x * 64, x1, x2);
}

// ======================================================================
// etime body (3-term bf16): Ah[128][20], Al+2560, Bh[64][20]+5120, Bl+6400 -> 7680
// ======================================================================
__device__ __forceinline__ void etime_body(uint32_t* pool, int b, int ks, int n0)
{
    uint32_t* Ah = pool;
    uint32_t* Al = pool + 2560;
    uint32_t* Bh = pool + 5120;
    uint32_t* Bl = pool + 6400;
    int kbeg = ks * (NPIX / ETSPLIT);
    const float* __restrict__ Tm = g_PRE[2][b];
    const float* __restrict__ Pm = g_PRE[3][b];

    int tid = threadIdx.x;
    int wid = tid >> 5, lane = tid & 31;
    int g = lane >> 2, tig = lane & 3;
    int wm = (wid & 3) * 32, wn = (wid >> 2) * 32;

    int am = tid >> 1, ak = (tid & 1) * 16;
    int bn = tid >> 2, bk = (tid & 3) * 8;

    float4 sA[4], sB[2];
    float c[2][4][4] = {};

    auto loadT = [&](int k0) {
#pragma unroll
        for (int q = 0; q < 4; q++) sA[q] = *(const float4*)&Tm[am * NPIX + k0 + ak + q * 4];
#pragma unroll
        for (int q = 0; q < 2; q++) sB[q] = *(const float4*)&Pm[(n0 + bn) * NPIX + k0 + bk + q * 4];
    };
    auto storeT = [&]() {
#pragma unroll
        for (int q = 0; q < 4; q++) {
            uint32_t h0,l0,h1,l1;
            split_pack(sA[q].x, sA[q].y, h0, l0);
            split_pack(sA[q].z, sA[q].w, h1, l1);
            int k2 = (ak >> 1) + q * 2;
            Ah[am * 20 + k2] = h0; Ah[am * 20 + k2 + 1] = h1;
            Al[am * 20 + k2] = l0; Al[am * 20 + k2 + 1] = l1;
        }
#pragma unroll
        for (int q = 0; q < 2; q++) {
            uint32_t h0,l0,h1,l1;
            split_pack(sB[q].x, sB[q].y, h0, l0);
            split_pack(sB[q].z, sB[q].w, h1, l1);
            int k2 = (bk >> 1) + q * 2;
            Bh[bn * 20 + k2] = h0; Bh[bn * 20 + k2 + 1] = h1;
            Bl[bn * 20 + k2] = l0; Bl[bn * 20 + k2 + 1] = l1;
        }
    };

    loadT(kbeg); storeT(); __syncthreads();
    for (int t = 0; t < 4; t++) {
        if (t < 3) loadT(kbeg + (t + 1) * 32);
#pragma unroll
        for (int kk2 = 0; kk2 < 16; kk2 += 8) {
            uint32_t ah[2][4], al[2][4];
#pragma unroll
            for (int mi = 0; mi < 2; mi++) {
                int mr = wm + mi * 16;
                ah[mi][0]=Ah[(mr+g  )*20+kk2+tig  ]; ah[mi][1]=Ah[(mr+g+8)*20+kk2+tig  ];
                ah[mi][2]=Ah[(mr+g  )*20+kk2+tig+4]; ah[mi][3]=Ah[(mr+g+8)*20+kk2+tig+4];
                al[mi][0]=Al[(mr+g  )*20+kk2+tig  ]; al[mi][1]=Al[(mr+g+8)*20+kk2+tig  ];
                al[mi][2]=Al[(mr+g  )*20+kk2+tig+4]; al[mi][3]=Al[(mr+g+8)*20+kk2+tig+4];
            }
#pragma unroll
            for (int ni = 0; ni < 4; ni++) {
                int nr = wn + ni * 8 + g;
                uint32_t bh[2], bl[2];
                bh[0]=Bh[nr*20+kk2+tig]; bh[1]=Bh[nr*20+kk2+tig+4];
                bl[0]=Bl[nr*20+kk2+tig]; bl[1]=Bl[nr*20+kk2+tig+4];
#pragma unroll
                for (int mi = 0; mi < 2; mi++) {
                    mma16bf(c[mi][ni], ah[mi], bh);
                    mma16bf(c[mi][ni], ah[mi], bl);
                    mma16bf(c[mi][ni], al[mi], bh);
                }
            }
        }
        __syncthreads();
        if (t < 3) storeT();
        __syncthreads();
    }

    float* outp = g_ETpart[b][ks];
#pragma unroll
    for (int mi = 0; mi < 2; mi++) {
#pragma unroll
        for (int ni = 0; ni < 4; ni++) {
            int row = wm + mi * 16 + g;
            int col = n0 + wn + ni * 8 + tig * 2;
            *(float2*)&outp[row * CI + col]       = make_float2(c[mi][ni][0], c[mi][ni][1]);
            *(float2*)&outp[(row + 8) * CI + col] = make_float2(c[mi][ni][2], c[mi][ni][3]);
        }
    }
}

// ======================================================================
// espace body (3-term bf16): Ah[16][136]=2176, Al+2176, Bh[16][72]+4352, Bl+5504 -> 6656
// ======================================================================
__device__ __forceinline__ void espace_body(uint32_t* pool, int b, int row0, int col0)
{
    uint32_t* Ah = pool;
    uint32_t* Al = pool + 2176;
    uint32_t* Bh = pool + 4352;
    uint32_t* Bl = pool + 5504;
    const float* __restrict__ T = g_PRE[2][b];
    const float* __restrict__ P = g_PRE[3][b];

    int tid = threadIdx.x;
    int wid = tid >> 5, lane = tid & 31;
    int g = lane >> 2, tig = lane & 3;
    int wm = (wid & 3) * 32, wn = (wid >> 2) * 32;

    int ak2 = tid >> 5, an4 = (tid & 31) * 4;
    int bk2 = tid >> 4, bm4 = (tid & 15) * 4;

    float4 sAe[2], sAo[2], sBe, sBo;
    float c[2][4][4] = {};

    auto loadT = [&](int k0) {
#pragma unroll
        for (int it = 0; it < 2; it++) {
            const float* te = &T[(k0 + 2 * (ak2 + it * 8)) * NPIX + row0 + an4];
            sAe[it] = *(const float4*)te;
            sAo[it] = *(const float4*)(te + NPIX);
        }
        const float* pe = &P[(k0 + 2 * bk2) * NPIX + col0 + bm4];
        sBe = *(const float4*)pe;
        sBo = *(const float4*)(pe + NPIX);
    };
    auto storeT = [&]() {
#pragma unroll
        for (int it = 0; it < 2; it++) {
            uint32_t h0,l0,h1,l1,h2,l2,h3,l3;
            split_pack(sAe[it].x, sAo[it].x, h0, l0); split_pack(sAe[it].y, sAo[it].y, h1, l1);
            split_pack(sAe[it].z, sAo[it].z, h2, l2); split_pack(sAe[it].w, sAo[it].w, h3, l3);
            int r = ak2 + it * 8;
            *(uint4*)&Ah[r * 136 + an4] = make_uint4(h0, h1, h2, h3);
            *(uint4*)&Al[r * 136 + an4] = make_uint4(l0, l1, l2, l3);
        }
        uint32_t h0,l0,h1,l1,h2,l2,h3,l3;
        split_pack(sBe.x, sBo.x, h0, l0); split_pack(sBe.y, sBo.y, h1, l1);
        split_pack(sBe.z, sBo.z, h2, l2); split_pack(sBe.w, sBo.w, h3, l3);
        *(uint4*)&Bh[bk2 * 72 + bm4] = make_uint4(h0, h1, h2, h3);
        *(uint4*)&Bl[bk2 * 72 + bm4] = make_uint4(l0, l1, l2, l3);
    };

    loadT(0); storeT(); __syncthreads();
    for (int t = 0; t < 4; t++) {
        if (t < 3) loadT((t + 1) * 32);
#pragma unroll
        for (int kk2 = 0; kk2 < 16; kk2 += 8) {
            uint32_t ah[2][4], al[2][4];
#pragma unroll
            for (int mi = 0; mi < 2; mi++) {
                int mr = wm + mi * 16;
                ah[mi][0] = Ah[(kk2+tig  )*136 + mr + g    ];
                ah[mi][1] = Ah[(kk2+tig  )*136 + mr + g + 8];
                ah[mi][2] = Ah[(kk2+tig+4)*136 + mr + g    ];
                ah[mi][3] = Ah[(kk2+tig+4)*136 + mr + g + 8];
                al[mi][0] = Al[(kk2+tig  )*136 + mr + g    ];
                al[mi][1] = Al[(kk2+tig  )*136 + mr + g + 8];
                al[mi][2] = Al[(kk2+tig+4)*136 + mr + g    ];
                al[mi][3] = Al[(kk2+tig+4)*136 + mr + g + 8];
            }
#pragma unroll
            for (int ni = 0; ni < 4; ni++) {
                uint32_t bh[2], bl[2];
                bh[0] = Bh[(kk2+tig  )*72 + wn + ni*8 + g];
                bh[1] = Bh[(kk2+tig+4)*72 + wn + ni*8 + g];
                bl[0] = Bl[(kk2+tig  )*72 + wn + ni*8 + g];
                bl[1] = Bl[(kk2+tig+4)*72 + wn + ni*8 + g];
#pragma unroll
                for (int mi = 0; mi < 2; mi++) {
                    mma16bf(c[mi][ni], ah[mi], bh);
                    mma16bf(c[mi][ni], ah[mi], bl);
                    mma16bf(c[mi][ni], al[mi], bh);
                }
            }
        }
        __syncthreads();
        if (t < 3) storeT();
        __syncthreads();
    }

    float* Ep = g_E[b];
#pragma unroll
    for (int mi = 0; mi < 2; mi++) {
#pragma unroll
        for (int ni = 0; ni < 4; ni++) {
            int row = row0 + wm + mi * 16 + g;
            int col = col0 + wn + ni * 8 + tig * 2;
            *(float2*)&Ep[row * NPIX + col]       = make_float2(c[mi][ni][0], c[mi][ni][1]);
            *(float2*)&Ep[(row + 8) * NPIX + col] = make_float2(c[mi][ni][2], c[mi][ni][3]);
        }
    }
}

// ======================================================================
// BIG3: espace (2592) | etime (144) | pre i=0,1 (288) = 3024 blocks
// ======================================================================
__global__ void __launch_bounds__(256) k_big3(const float* __restrict__ x1,
                                              const float* __restrict__ x2)
{
    __shared__ uint32_t pool[7680];
    int bx = blockIdx.x;
    if (bx < 2592) {
        int x = bx % 36, y = (bx / 36) % 18, b = bx / 648;
        espace_body(pool, b, y * 128, x * 64);
    } else if (bx < 2736) {
        int idx = bx - 2592;
        int x = idx % 2, ks = (idx / 2) % 18, b = idx / 36;
        etime_body(pool, b, ks, x * 64);
    } else {
        int idx = bx - 2736;
        int x = idx % 36, iz = idx / 36;
        pre_body(pool, iz >> 2, iz & 3, x * 64, x1, x2);
    }
}

// ======================================================================
// k_softmaxET: fused etreduce + softmax_time. warp per row/col.
// grid (32, BATCH) x 256.
// ======================================================================
__global__ void __launch_bounds__(256) k_softmaxET()
{
    int b = blockIdx.y;
    int wg = blockIdx.x * 8 + (threadIdx.x >> 5);
    int lane = threadIdx.x & 31;
    int t = wg & 127;
    int orient = wg >> 7;   // 0: row softmax -> A2 ; 1: col softmax -> A1
    float v[4];
#pragma unroll
    for (int j = 0; j < 4; j++) {
        int d = lane + j * 32;
        float s = 0.f;
#pragma unroll
        for (int p = 0; p < ETSPLIT; p++)
            s += orient ? g_ETpart[b][p][d * CI + t] : g_ETpart[b][p][t * CI + d];
        v[j] = s;
    }
    float mx = fmaxf(fmaxf(v[0], v[1]), fmaxf(v[2], v[3]));
#pragma unroll
    for (int off = 16; off; off >>= 1) mx = fmaxf(mx, __shfl_xor_sync(0xffffffffu, mx, off));
    float e0 = __expf(v[0] - mx), e1 = __expf(v[1] - mx);
    float e2 = __expf(v[2] - mx), e3 = __expf(v[3] - mx);
    float sum = e0 + e1 + e2 + e3;
#pragma unroll
    for (int off = 16; off; off >>= 1) sum += __shfl_xor_sync(0xffffffffu, sum, off);
    float rs = 1.f / sum;
    float* dst = (orient ? g_A1[b] : g_A2[b]) + t * CI;
    dst[lane]      = e0 * rs;
    dst[lane + 32] = e1 * rs;
    dst[lane + 64] = e2 * rs;
    dst[lane + 96] = e3 * rs;
}

// ======================================================================
// zgemm body: 3-term bf16, K=128, 128x64, pipelined. Pool carve == pre.
// ======================================================================
__device__ __forceinline__ void zgemm_body(uint32_t* pool, int zi, int b, int n0)
{
    uint32_t* Ah = pool;
    uint32_t* Al = pool + 2560;
    uint32_t* Bh = pool + 5120;
    uint32_t* Bl = pool + 6272;
    const float* __restrict__ Asrc = zi ? g_A2[b] : g_A1[b];
    const float* __restrict__ Bsrc = g_PRE[zi][b];

    int tid = threadIdx.x;
    int wid = tid >> 5, lane = tid & 31;
    int g = lane >> 2, tig = lane & 3;
    int wm = (wid & 3) * 32, wn = (wid >> 2) * 32;

    int am = tid >> 1, ak = (tid & 1) * 16;
    int bk2 = tid >> 4, bn4 = (tid & 15) * 4;

    float4 sA[4], sbe, sbo;
    float c[2][4][4] = {};

    auto loadT = [&](int k0) {
#pragma unroll
        for (int q = 0; q < 4; q++) sA[q] = *(const float4*)&Asrc[am * CI + k0 + ak + q * 4];
        const float* be = &Bsrc[(k0 + 2 * bk2) * NPIX + n0 + bn4];
        sbe = *(const float4*)be;
        sbo = *(const float4*)(be + NPIX);
    };
    auto storeT = [&]() {
#pragma unroll
        for (int q = 0; q < 4; q++) {
            uint32_t h0,l0,h1,l1;
            split_pack(sA[q].x, sA[q].y, h0, l0);
            split_pack(sA[q].z, sA[q].w, h1, l1);
            int k2 = (ak >> 1) + q * 2;
            Ah[am * 20 + k2] = h0; Ah[am * 20 + k2 + 1] = h1;
            Al[am * 20 + k2] = l0; Al[am * 20 + k2 + 1] = l1;
        }
        uint32_t h0,l0,h1,l1,h2,l2,h3,l3;
        split_pack(sbe.x, sbo.x, h0, l0); split_pack(sbe.y, sbo.y, h1, l1);
        split_pack(sbe.z, sbo.z, h2, l2); split_pack(sbe.w, sbo.w, h3, l3);
        *(uint4*)&Bh[bk2 * 72 + bn4] = make_uint4(h0, h1, h2, h3);
        *(uint4*)&Bl[bk2 * 72 + bn4] = make_uint4(l0, l1, l2, l3);
    };

    loadT(0); storeT(); __syncthreads();
    for (int t = 0; t < 4; t++) {
        if (t < 3) loadT((t + 1) * 32);
#pragma unroll
        for (int kk2 = 0; kk2 < 16; kk2 += 8) {
            uint32_t ah[2][4], al[2][4];
#pragma unroll
            for (int mi = 0; mi < 2; mi++) {
                int mr = wm + mi * 16;
                ah[mi][0]=Ah[(mr+g  )*20+kk2+tig  ]; ah[mi][1]=Ah[(mr+g+8)*20+kk2+tig  ];
                ah[mi][2]=Ah[(mr+g  )*20+kk2+tig+4]; ah[mi][3]=Ah[(mr+g+8)*20+kk2+tig+4];
                al[mi][0]=Al[(mr+g  )*20+kk2+tig  ]; al[mi][1]=Al[(mr+g+8)*20+kk2+tig  ];
                al[mi][2]=Al[(mr+g  )*20+kk2+tig+4]; al[mi][3]=Al[(mr+g+8)*20+kk2+tig+4];
            }
#pragma unroll
            for (int ni = 0; ni < 4; ni++) {
                uint32_t bh[2], bl[2];
                bh[0]=Bh[(kk2+tig  )*72+wn+ni*8+g]; bh[1]=Bh[(kk2+tig+4)*72+wn+ni*8+g];
                bl[0]=Bl[(kk2+tig  )*72+wn+ni*8+g]; bl[1]=Bl[(kk2+tig+4)*72+wn+ni*8+g];
#pragma unroll
                for (int mi = 0; mi < 2; mi++) {
                    mma16bf(c[mi][ni], ah[mi], bh);
                    mma16bf(c[mi][ni], ah[mi], bl);
                    mma16bf(c[mi][ni], al[mi], bh);
                }
            }
        }
        __syncthreads();
        if (t < 3) storeT();
        __syncthreads();
    }

    float* Zout = g_Z[zi][b];
#pragma unroll
    for (int mi = 0; mi < 2; mi++) {
#pragma unroll
        for (int ni = 0; ni < 4; ni++) {
            int row = wm + mi * 16 + g;
            int col = n0 + wn + ni * 8 + tig * 2;
            *(float2*)&Zout[row * NPIX + col]       = make_float2(c[mi][ni][0], c[mi][ni][1]);
            *(float2*)&Zout[(row + 8) * NPIX + col] = make_float2(c[mi][ni][2], c[mi][ni][3]);
        }
    }
}

// ---------------- stats bodies ----------------
__device__ __forceinline__ void colpart_body(int b, int ch, int m)
{
    const float* Ep = g_E[b];
    float mx = -3.0e38f, s = 0.f;
    int n0 = ch * (NPIX / NCHUNK);
    for (int n = n0; n < n0 + NPIX / NCHUNK; n++) {
        float v = Ep[(size_t)n * NPIX + m];
        if (v > mx) { s = s * __expf(mx - v) + 1.f; mx = v; }
        else        { s += __expf(v - mx); }
    }
    g_pmax[b][ch][m] = mx;
    g_psum[b][ch][m] = s;
}

__device__ __forceinline__ void rowstats_body(int b, int n, int lane)
{
    const float* row = g_E[b] + (size_t)n * NPIX;
    float mx = -3.0e38f, s = 0.f;
    for (int m = lane; m < NPIX; m += 32) {
        float v = row[m];
        if (v > mx) { s = s * __expf(mx - v) + 1.f; mx = v; }
        else        { s += __expf(v - mx); }
    }
#pragma unroll
    for (int off = 16; off; off >>= 1) {
        float om = __shfl_xor_sync(0xffffffffu, mx, off);
        float os = __shfl_xor_sync(0xffffffffu, s, off);
        float nm = fmaxf(mx, om);
        s = s * __expf(mx - nm) + os * __expf(om - nm);
        mx = nm;
    }
    if (lane == 0) { g_rowmax[b][n] = mx; g_rowrsum[b][n] = 1.f / s; }
}

// ======================================================================
// ZPS: zgemm (288) | colpart (648) | rowstats (1152) = 2088 blocks
// ======================================================================
__global__ void __launch_bounds__(256) k_zps()
{
    __shared__ uint32_t pool[7424];
    int bx = blockIdx.x;
    if (bx < 288) {
        int x = bx % 36, iz = bx / 36;
        zgemm_body(pool, iz >> 2, iz & 3, x * 64);
    } else if (bx < 936) {
        int idx = bx - 288;
        int mb = idx % 9, ch = (idx / 9) % 18, b = idx / 162;
        colpart_body(b, ch, mb * 256 + threadIdx.x);
    } else {
        int idx = bx - 936;
        int xb = idx % 288, b = idx / 288;
        rowstats_body(b, xb * 8 + (threadIdx.x >> 5), threadIdx.x & 31);
    }
}

__global__ void k_colreduce()
{
    int b = blockIdx.y, m = blockIdx.x * 256 + threadIdx.x;
    float mx = -3.0e38f, s = 0.f;
#pragma unroll
    for (int ch = 0; ch < NCHUNK; ch++) {
        float pm = g_pmax[b][ch][m], ps = g_psum[b][ch][m];
        float nm = fmaxf(mx, pm);
        s = s * __expf(mx - nm) + ps * __expf(pm - nm);
        mx = nm;
    }
    g_colmax[b][m] = mx;
    g_colrsum[b][m] = 1.f / s;
}

// ======================================================================
// k_ygemm_bf16 (R8, unchanged): single-pass bf16, fused exp
// ======================================================================
__global__ void __launch_bounds__(256) k_ygemm_bf16()
{
    int yi = blockIdx.z >> 2, b = blockIdx.z & 3;
    int n0 = blockIdx.x * 64;
    const float* __restrict__ Zp = g_Z[yi][b];
    const float* __restrict__ Ep = g_E[b];
    const float* __restrict__ vmax = yi ? g_rowmax[b]  : g_colmax[b];
    const float* __restrict__ vrs  = yi ? g_rowrsum[b] : g_colrsum[b];

    __shared__ uint32_t A2[128][20];
    __shared__ uint32_t Bs[1280];
    __shared__ float s_max[64], s_rs[64];

    int tid = threadIdx.x;
    if (tid < 64) { s_max[tid] = vmax[n0 + tid]; s_rs[tid] = vrs[n0 + tid]; }
    __syncthreads();

    int wid = tid >> 5, lane = tid & 31;
    int g = lane >> 2, tig = lane & 3;
    int wm = (wid & 3) * 32, wn = (wid >> 2) * 32;

    int am = tid >> 1, aks = (tid & 1) * 16;
    int bk2g = tid >> 4, bn4 = (tid & 15) * 4;
    int bj = tid >> 2, bkq = (tid & 3) * 8;

    float4 sA[4], sB0, sB1;
    float c[2][4][4] = {};

    auto loadT = [&](int k0) {
#pragma unroll
        for (int q = 0; q < 4; q++) sA[q] = *(const float4*)&Zp[am * NPIX + k0 + aks + q * 4];
        if (yi == 0) {
            const float* be = &Ep[(size_t)(k0 + 2 * bk2g) * NPIX + n0 + bn4];
            sB0 = *(const float4*)be;
            sB1 = *(const float4*)(be + NPIX);
        } else {
            const float* be = &Ep[(size_t)(n0 + bj) * NPIX + k0 + bkq];
            sB0 = *(const float4*)be;
            sB1 = *(const float4*)(be + 4);
        }
    };
    auto storeT = [&]() {
        int k2b = aks >> 1;
#pragma unroll
        for (int q = 0; q < 4; q++) {
            A2[am][k2b + q * 2    ] = pack_bf(sA[q].x, sA[q].y);
            A2[am][k2b + q * 2 + 1] = pack_bf(sA[q].z, sA[q].w);
        }
        if (yi == 0) {
            float m0v = s_max[bn4], m1v = s_max[bn4+1], m2v = s_max[bn4+2], m3v = s_max[bn4+3];
            *(uint4*)&Bs[bk2g * 72 + bn4] = make_uint4(
                pack_bf(__expf(sB0.x - m0v), __expf(sB1.x - m0v)),
                pack_bf(__expf(sB0.y - m1v), __expf(sB1.y - m1v)),
                pack_bf(__expf(sB0.z - m2v), __expf(sB1.z - m2v)),
                pack_bf(__expf(sB0.w - m3v), __expf(sB1.w - m3v)));
        } else {
            float mx = s_max[bj];
            *(uint4*)&Bs[bj * 20 + (bkq >> 1)] = make_uint4(
                pack_bf(__expf(sB0.x - mx), __expf(sB0.y - mx)),
                pack_bf(__expf(sB0.z - mx), __expf(sB0.w - mx)),
                pack_bf(__expf(sB1.x - mx), __expf(sB1.y - mx)),
                pack_bf(__expf(sB1.z - mx), __expf(sB1.w - mx)));
        }
    };

    loadT(0); storeT(); __syncthreads();
    for (int t = 0; t < 72; t++) {
        if (t < 71) loadT((t + 1) * 32);
#pragma unroll
        for (int kk2 = 0; kk2 < 16; kk2 += 8) {
            uint32_t a[2][4];
#pragma unroll
            for (int mi = 0; mi < 2; mi++) {
                int mr = wm + mi * 16;
                a[mi][0]=A2[mr+g  ][kk2+tig  ]; a[mi][1]=A2[mr+g+8][kk2+tig  ];
                a[mi][2]=A2[mr+g  ][kk2+tig+4]; a[mi][3]=A2[mr+g+8][kk2+tig+4];
            }
#pragma unroll
            for (int ni = 0; ni < 4; ni++) {
                uint32_t bb[2];
                if (yi == 0) {
                    bb[0] = Bs[(kk2+tig  ) * 72 + wn + ni*8 + g];
                    bb[1] = Bs[(kk2+tig+4) * 72 + wn + ni*8 + g];
                } else {
                    int nr = wn + ni * 8 + g;
                    bb[0] = Bs[nr * 20 + kk2 + tig    ];
                    bb[1] = Bs[nr * 20 + kk2 + tig + 4];
                }
                mma16bf(c[0][ni], a[0], bb);
                mma16bf(c[1][ni], a[1], bb);
            }
        }
        __syncthreads();
        if (t < 71) storeT();
        __syncthreads();
    }

    float* Yp = g_Y[yi][b];
#pragma unroll
    for (int mi = 0; mi < 2; mi++) {
#pragma unroll
        for (int ni = 0; ni < 4; ni++) {
            int row = wm + mi * 16 + g;
            int col = wn + ni * 8 + tig * 2;
            float r0 = s_rs[col], r1 = s_rs[col + 1];
            *(float2*)&Yp[row * NPIX + n0 + col] =
                make_float2(c[mi][ni][0] * r0, c[mi][ni][1] * r1);
            *(float2*)&Yp[(row + 8) * NPIX + n0 + col] =
                make_float2(c[mi][ni][2] * r0, c[mi][ni][3] * r1);
        }
    }
}

// ======================================================================
// k_post_mma (R8, unchanged tf32)
// ======================================================================
__global__ void __launch_bounds__(256) k_post_mma(const float* __restrict__ x1,
                                                  const float* __restrict__ x2,
                                                  float* __restrict__ out)
{
    int i = blockIdx.z >> 2, b = blockIdx.z & 3;
    int m0 = blockIdx.y * 128, n0 = blockIdx.x * 64;
    const float* __restrict__ Asrc = g_Wpost[i];
    const float* __restrict__ Bsrc = g_Y[i][b];

    __shared__ uint32_t As[128][36];
    __shared__ uint32_t Bs[32][72];

    int tid = threadIdx.x;
    int wid = tid >> 5, lane = tid & 31;
    int g = lane >> 2, tig = lane & 3;
    int wm = (wid & 3) * 32, wn = (wid >> 2) * 32;

    int am = tid >> 1, ak = (tid & 1) * 16;
    int bkk = tid >> 3, bjq = (tid & 7) * 8;

    float4 sA[4], sB[2];
    float c[2][4][4] = {};

    auto loadT = [&](int k0) {
#pragma unroll
        for (int q = 0; q < 4; q++) sA[q] = *(const float4*)&Asrc[(m0 + am) * CI + k0 + ak + q * 4];
#pragma unroll
        for (int q = 0; q < 2; q++) sB[q] = *(const float4*)&Bsrc[(k0 + bkk) * NPIX + n0 + bjq + q * 4];
    };
    auto storeT = [&]() {
#pragma unroll
        for (int q = 0; q < 4; q++) {
            *(uint4*)&As[am][ak + q * 4] = make_uint4(
                f2t(sA[q].x), f2t(sA[q].y), f2t(sA[q].z), f2t(sA[q].w));
        }
#pragma unroll
        for (int q = 0; q < 2; q++) {
            *(uint4*)&Bs[bkk][bjq + q * 4] = make_uint4(
                f2t(sB[q].x), f2t(sB[q].y), f2t(sB[q].z), f2t(sB[q].w));
        }
    };

    loadT(0); storeT(); __syncthreads();
    for (int t = 0; t < 4; t++) {
        if (t < 3) loadT((t + 1) * 32);
#pragma unroll
        for (int kk = 0; kk < 32; kk += 8) {
            uint32_t a[2][4];
#pragma unroll
            for (int mi = 0; mi < 2; mi++) {
                int mr = wm + mi * 16;
                a[mi][0]=As[mr+g  ][kk+tig  ]; a[mi][1]=As[mr+g+8][kk+tig  ];
                a[mi][2]=As[mr+g  ][kk+tig+4]; a[mi][3]=As[mr+g+8][kk+tig+4];
            }
#pragma unroll
            for (int ni = 0; ni < 4; ni++) {
                uint32_t bb[2];
                bb[0]=Bs[kk+tig  ][wn+ni*8+g];
                bb[1]=Bs[kk+tig+4][wn+ni*8+g];
                mma8(c[0][ni], a[0], bb);
                mma8(c[1][ni], a[1], bb);
            }
        }
        __syncthreads();
        if (t < 3) storeT();
        __syncthreads();
    }

    const float* xs = (i ? x2 : x1) + b * CC * NPIX;
    float* op = out + (size_t)i * BATCH * CC * NPIX + (size_t)b * CC * NPIX;
#pragma unroll
    for (int mi = 0; mi < 2; mi++) {
#pragma unroll
        for (int ni = 0; ni < 4; ni++) {
            int row = m0 + wm + mi * 16 + g;
            int col = n0 + wn + ni * 8 + tig * 2;
            float b0 = g_bpost[i][row], b1 = g_bpost[i][row + 8];
            float2 r0 = *(const float2*)&xs[row * NPIX + col];
            float2 r1 = *(const float2*)&xs[(row + 8) * NPIX + col];
            *(float2*)&op[row * NPIX + col] =
                make_float2(c[mi][ni][0] + b0 + r0.x, c[mi][ni][1] + b0 + r0.y);
            *(float2*)&op[(row + 8) * NPIX + col] =
                make_float2(c[mi][ni][2] + b1 + r1.x, c[mi][ni][3] + b1 + r1.y);
        }
    }
}

// ---------------- launcher ----------------
extern "C" void kernel_launch(void* const* d_in, const int* in_sizes, int n_in,
                              void* d_out, int out_size)
{
    const float* x1      = (const float*)d_in[0];
    const float* x2      = (const float*)d_in[1];
    const float* bn_pre  = (const float*)d_in[2];
    const float* w_pre   = (const float*)d_in[3];
    const float* b_pre   = (const float*)d_in[4];
    const float* w_post  = (const float*)d_in[5];
    const float* b_post  = (const float*)d_in[6];
    const float* bn_post = (const float*)d_in[7];
    float* out = (float*)d_out;

    k_fold<<<128, 256>>>(bn_pre, w_pre, b_pre, w_post, b_post, bn_post);
    k_pre23<<<dim3(36, 1, 8), 256>>>(x1, x2);
    k_big3<<<3024, 256>>>(x1, x2);
    k_softmaxET<<<dim3(32, BATCH), 256>>>();
    k_zps<<<2088, 256>>>();
    k_colreduce<<<dim3(9, BATCH), 256>>>();
    k_ygemm_bf16<<<dim3(36, 1, 8), 256>>>();
    k_post_mma<<<dim3(36, 2, 8), 256>>>(x1, x2, out);
}